// round 1
// baseline (speedup 1.0000x reference)
#include <cuda_runtime.h>

// Problem constants
#define CH      256
#define G_      16
#define GROUP_CH 16
#define KK      9
#define RROWS   144      // K*K*G
#define RED_CH  128      // CH/RED
#define B_      8
#define HWD     64
#define HW      4096     // 64*64

// ---------------- device scratch (static allocation — allowed) -------------
__device__ float g_Wc[RROWS * CH];      // fused weight  (144x256)
__device__ float g_bc[RROWS];           // fused bias
__device__ float g_ker[B_ * RROWS * HW];    // 18.9 MB  ker[b][144][64][64]
__device__ float g_Kp[B_ * G_ * 3 * HW];    //  6.3 MB  Kp[b][g][kj][64][64]

// ---------------- kernel A: Wc = W_span @ W_reduce, bc = Wspan@b_red + b_span
__global__ void fuse_weights(const float* __restrict__ W_reduce,
                             const float* __restrict__ b_reduce,
                             const float* __restrict__ W_span,
                             const float* __restrict__ b_span) {
    __shared__ float ws[RED_CH];
    const int r = blockIdx.x;           // 0..143
    const int t = threadIdx.x;          // 128 threads
    ws[t] = W_span[r * RED_CH + t];
    __syncthreads();
    #pragma unroll
    for (int cc = 0; cc < 2; cc++) {
        const int c = t + cc * 128;
        float s = 0.f;
        #pragma unroll 8
        for (int o = 0; o < RED_CH; o++) s += ws[o] * W_reduce[o * CH + c];
        g_Wc[r * CH + c] = s;
    }
    if (t == 0) {
        float s = 0.f;
        for (int o = 0; o < RED_CH; o++) s += ws[o] * b_reduce[o];
        g_bc[r] = s + b_span[r];
    }
}

// ---------------- kernel B: g_ker[b][r][hw] = sum_c Wc[r][c]*x[b][c][hw] + bc
// Tiles: BM=48, BN=128, BK=32. 256 threads, 6x4 per thread.
#define BM 48
#define BN 128
#define BK 32
__global__ __launch_bounds__(256) void ker_gemm(const float* __restrict__ x) {
    __shared__ float As[BK][BM + 1];    // [k][m]  (transposed, pad 49)
    __shared__ float Bs[BK][BN];
    const int b    = blockIdx.z;
    const int r0   = blockIdx.y * BM;   // 0,48,96
    const int n0   = blockIdx.x * BN;   // hw tile
    const int tid  = threadIdx.x;
    const int tm   = tid >> 5;          // 0..7
    const int tn   = tid & 31;          // 0..31
    const float* xb = x + (size_t)b * CH * HW;

    float acc[6][4];
    #pragma unroll
    for (int p = 0; p < 6; p++)
        #pragma unroll
        for (int q = 0; q < 4; q++) acc[p][q] = 0.f;

    for (int k0 = 0; k0 < CH; k0 += BK) {
        __syncthreads();
        // load Wc tile 48x32, transpose into As[y][x]
        #pragma unroll
        for (int it = 0; it < 6; it++) {
            const int e  = tid + 256 * it;       // < 1536
            const int xr = e >> 5, y = e & 31;
            As[y][xr] = g_Wc[(r0 + xr) * CH + k0 + y];
        }
        // load x tile 32x128 as float4
        #pragma unroll
        for (int it = 0; it < 4; it++) {
            const int e4 = tid + 256 * it;       // < 1024
            const int kk = e4 >> 5, n4 = e4 & 31;
            float4 v = *reinterpret_cast<const float4*>(&xb[(size_t)(k0 + kk) * HW + n0 + n4 * 4]);
            *reinterpret_cast<float4*>(&Bs[kk][n4 * 4]) = v;
        }
        __syncthreads();
        #pragma unroll
        for (int kk = 0; kk < BK; kk++) {
            float a[6], bb[4];
            float4 bv = *reinterpret_cast<const float4*>(&Bs[kk][tn * 4]);
            bb[0] = bv.x; bb[1] = bv.y; bb[2] = bv.z; bb[3] = bv.w;
            #pragma unroll
            for (int p = 0; p < 6; p++) a[p] = As[kk][tm * 6 + p];
            #pragma unroll
            for (int p = 0; p < 6; p++)
                #pragma unroll
                for (int q = 0; q < 4; q++) acc[p][q] += a[p] * bb[q];
        }
    }
    #pragma unroll
    for (int p = 0; p < 6; p++) {
        const int r = r0 + tm * 6 + p;
        const float bias = g_bc[r];
        float4 v = make_float4(acc[p][0] + bias, acc[p][1] + bias,
                               acc[p][2] + bias, acc[p][3] + bias);
        *reinterpret_cast<float4*>(&g_ker[((size_t)b * RROWS + r) * HW + n0 + tn * 4]) = v;
    }
}

// ---------------- kernel fold: Kp[b][g][kj][i][m] = sum_ki ker[g*9+ki*3+kj][i][m-(ki-1)]
__global__ void fold_ker() {
    const int idx = blockIdx.x * 256 + threadIdx.x;   // < 8*16*3*4096 = 1572864
    const int m  = idx & 63;
    const int i  = (idx >> 6) & 63;
    const int t  = idx >> 12;            // bg*3 + kj
    const int kj = t % 3;
    const int bg = t / 3;
    const int b  = bg >> 4, g = bg & 15;
    const float* base = g_ker + ((size_t)b * RROWS + g * KK) * HW + i * HWD;
    float v = base[(3 + kj) * HW + m];                 // ki=1
    if (m < 63) v += base[(0 + kj) * HW + m + 1];      // ki=0
    if (m > 0)  v += base[(6 + kj) * HW + m - 1];      // ki=2
    g_Kp[idx] = v;
}

// ---------------- kernel C: out[b, g*16+c, i, j] = sum_{kj,m} Kp[b,g,kj,i,m] * x[b,gc, m, j+kj-1]
// Per CTA: one (b, g, 4-channel quarter). Out tile 64(i) x 256(c,j). 256 thr, 8x8/thread.
#define XSTR 72
#define XCH  (64 * 72)     // 4608 floats per channel
#define ASTR 68
#define SMEM_C_BYTES ((4 * XCH + 64 * ASTR) * 4)   // 91136

__global__ __launch_bounds__(256, 2) void inv_main(const float* __restrict__ x,
                                                   float* __restrict__ out) {
    extern __shared__ float sm[];
    float* xs = sm;                 // 4 channels, halo cols 3 and 68, data at 4..67
    float* As = sm + 4 * XCH;       // 64 x ASTR

    const int cq = blockIdx.x;      // 0..3
    const int g  = blockIdx.y;      // 0..15
    const int b  = blockIdx.z;      // 0..7
    const int tid = threadIdx.x;
    const int ti  = tid >> 5;       // 0..7  (i group)
    const int tn  = tid & 31;       // 0..31 (j within half-row)
    const int ch0 = g * GROUP_CH + cq * 4;
    const float* xb = x + ((size_t)b * CH + ch0) * HW;

    // zero halo columns (j+kj-1 == -1 -> col 3 ; == 64 -> col 68)
    {
        const int c = tid >> 6, m = tid & 63;
        xs[c * XCH + m * XSTR + 3]  = 0.f;
        xs[c * XCH + m * XSTR + 68] = 0.f;
    }
    // load 4 x-channels (4096 float4 total, 16 per thread)
    #pragma unroll
    for (int it = 0; it < 16; it++) {
        const int e4 = tid + 256 * it;
        const int c  = e4 >> 10;
        const int f  = e4 & 1023;
        const int m  = f >> 4, w4 = f & 15;
        float4 v = *reinterpret_cast<const float4*>(&xb[(size_t)c * HW + m * HWD + w4 * 4]);
        *reinterpret_cast<float4*>(&xs[c * XCH + m * XSTR + 4 + w4 * 4]) = v;
    }

    float acc[8][8];
    #pragma unroll
    for (int p = 0; p < 8; p++)
        #pragma unroll
        for (int q = 0; q < 8; q++) acc[p][q] = 0.f;

    int xoff[8];
    #pragma unroll
    for (int q = 0; q < 8; q++)
        xoff[q] = (q >> 1) * XCH + 3 + tn + ((q & 1) << 5);   // c=q/2, j=tn or tn+32

    const float* Kpb = g_Kp + ((size_t)b * G_ + g) * 3 * HW;

    for (int kj = 0; kj < 3; kj++) {
        __syncthreads();
        // load Kp[b][g][kj] 64x64 tile (1024 float4, 4 per thread)
        #pragma unroll
        for (int it = 0; it < 4; it++) {
            const int e4 = tid + 256 * it;
            const int i  = e4 >> 4, m4 = e4 & 15;
            float4 v = *reinterpret_cast<const float4*>(&Kpb[kj * HW + i * HWD + m4 * 4]);
            *reinterpret_cast<float4*>(&As[i * ASTR + m4 * 4]) = v;
        }
        __syncthreads();
        #pragma unroll 2
        for (int m = 0; m < 64; m++) {
            float a[8], bb[8];
            #pragma unroll
            for (int p = 0; p < 8; p++) a[p] = As[(ti * 8 + p) * ASTR + m];   // warp broadcast
            #pragma unroll
            for (int q = 0; q < 8; q++) bb[q] = xs[xoff[q] + m * XSTR + kj]; // conflict-free
            #pragma unroll
            for (int p = 0; p < 8; p++)
                #pragma unroll
                for (int q = 0; q < 8; q++) acc[p][q] += a[p] * bb[q];
        }
    }

    // epilogue: out[((b*256 + g*16 + c) * 64 + i) * 64 + j]
    #pragma unroll
    for (int q = 0; q < 8; q++) {
        const int c = ch0 + (q >> 1);
        const int j = tn + ((q & 1) << 5);
        float* ob = out + (((size_t)b * CH + c) * HWD + ti * 8) * HWD + j;
        #pragma unroll
        for (int p = 0; p < 8; p++) ob[p * HWD] = acc[p][q];
    }
}

// ---------------- launch --------------------------------------------------
extern "C" void kernel_launch(void* const* d_in, const int* in_sizes, int n_in,
                              void* d_out, int out_size) {
    const float* x        = (const float*)d_in[0];
    const float* W_reduce = (const float*)d_in[1];
    const float* b_reduce = (const float*)d_in[2];
    const float* W_span   = (const float*)d_in[3];
    const float* b_span   = (const float*)d_in[4];
    float* out = (float*)d_out;

    // idempotent, non-stream API: safe every call (also during graph capture)
    cudaFuncSetAttribute(inv_main, cudaFuncAttributeMaxDynamicSharedMemorySize, SMEM_C_BYTES);

    fuse_weights<<<RROWS, 128>>>(W_reduce, b_reduce, W_span, b_span);
    ker_gemm<<<dim3(HW / BN, RROWS / BM, B_), 256>>>(x);
    fold_ker<<<(B_ * G_ * 3 * HW) / 256, 256>>>();
    inv_main<<<dim3(4, G_, B_), 256, SMEM_C_BYTES>>>(x, out);
}

// round 2
// speedup vs baseline: 1.4235x; 1.4235x over previous
#include <cuda_runtime.h>

typedef unsigned long long u64;

// Problem constants
#define CH      256
#define G_      16
#define KK      9
#define RROWS   144      // K*K*G
#define RED_CH  128      // CH/RED
#define B_      8
#define HWD     64
#define HW      4096     // 64*64

// ---------------- f32x2 helpers (Blackwell packed fp32) --------------------
__device__ __forceinline__ u64 ffma2(u64 a, u64 b, u64 c) {
    u64 d;
    asm("fma.rn.f32x2 %0, %1, %2, %3;" : "=l"(d) : "l"(a), "l"(b), "l"(c));
    return d;
}
__device__ __forceinline__ u64 pack2(float lo, float hi) {
    u64 d; asm("mov.b64 %0, {%1, %2};" : "=l"(d) : "f"(lo), "f"(hi)); return d;
}
__device__ __forceinline__ float2 unpack2(u64 v) {
    float2 r; asm("mov.b64 {%0, %1}, %2;" : "=f"(r.x), "=f"(r.y) : "l"(v)); return r;
}

// ---------------- device scratch -------------------------------------------
__device__ float g_Wc[RROWS * CH];
__device__ float g_bc[RROWS];
__device__ float g_ker[B_ * RROWS * HW];    // 18.9 MB
__device__ float g_Kp[B_ * G_ * 3 * HW];    //  6.3 MB

// ---------------- kernel A: fuse weights -----------------------------------
__global__ void fuse_weights(const float* __restrict__ W_reduce,
                             const float* __restrict__ b_reduce,
                             const float* __restrict__ W_span,
                             const float* __restrict__ b_span) {
    __shared__ float ws[RED_CH];
    const int r = blockIdx.x;
    const int t = threadIdx.x;          // 128
    ws[t] = W_span[r * RED_CH + t];
    __syncthreads();
    #pragma unroll
    for (int cc = 0; cc < 2; cc++) {
        const int c = t + cc * 128;
        float s = 0.f;
        #pragma unroll 8
        for (int o = 0; o < RED_CH; o++) s += ws[o] * W_reduce[o * CH + c];
        g_Wc[r * CH + c] = s;
    }
    if (t == 0) {
        float s = 0.f;
        for (int o = 0; o < RED_CH; o++) s += ws[o] * b_reduce[o];
        g_bc[r] = s + b_span[r];
    }
}

// ---------------- kernel B: ker = Wc @ x (FFMA2) ---------------------------
// BM=48, BN=128, BK=32. 128 threads, thread tile 12(i) x 4(n as 2 f32x2 pairs)
#define BM2 48
#define BN2 128
#define BK2 32
#define AST2 68      // floats per i-row in duplicated Wc smem (32k*2 + pad)

__global__ __launch_bounds__(128, 3) void ker_gemm2(const float* __restrict__ x) {
    __shared__ float Bs[BK2 * BN2];        // 16 KB
    __shared__ float As2[BM2 * AST2];      // 13 KB (Wc duplicated pairs, [i][k*2])
    const int b  = blockIdx.z;
    const int r0 = blockIdx.y * BM2;
    const int n0 = blockIdx.x * BN2;
    const int tid = threadIdx.x;
    const int tm  = tid >> 5;              // 0..3
    const int tn  = tid & 31;
    const float* xb = x + (size_t)b * CH * HW;

    float  wreg[12];
    float4 xreg[8];

    // prefetch tile k0=0
    #pragma unroll
    for (int it = 0; it < 12; it++) {
        const int e = tid + 128 * it, i = e >> 5, k = e & 31;
        wreg[it] = g_Wc[(r0 + i) * CH + k];
    }
    #pragma unroll
    for (int it = 0; it < 8; it++) {
        const int e4 = tid + 128 * it, k = e4 >> 5, n4 = (e4 & 31) * 4;
        xreg[it] = *(const float4*)&xb[(size_t)k * HW + n0 + n4];
    }

    u64 acc[12][2];
    #pragma unroll
    for (int p = 0; p < 12; p++) { acc[p][0] = 0ull; acc[p][1] = 0ull; }

    for (int k0 = 0; k0 < CH; k0 += BK2) {
        __syncthreads();
        #pragma unroll
        for (int it = 0; it < 12; it++) {
            const int e = tid + 128 * it, i = e >> 5, k = e & 31;
            *(u64*)&As2[i * AST2 + k * 2] = pack2(wreg[it], wreg[it]);
        }
        #pragma unroll
        for (int it = 0; it < 8; it++) {
            const int e4 = tid + 128 * it, k = e4 >> 5, n4 = (e4 & 31) * 4;
            *(float4*)&Bs[k * BN2 + n4] = xreg[it];
        }
        __syncthreads();
        if (k0 + BK2 < CH) {
            const int kn = k0 + BK2;
            #pragma unroll
            for (int it = 0; it < 12; it++) {
                const int e = tid + 128 * it, i = e >> 5, k = e & 31;
                wreg[it] = g_Wc[(r0 + i) * CH + kn + k];
            }
            #pragma unroll
            for (int it = 0; it < 8; it++) {
                const int e4 = tid + 128 * it, k = e4 >> 5, n4 = (e4 & 31) * 4;
                xreg[it] = *(const float4*)&xb[(size_t)(kn + k) * HW + n0 + n4];
            }
        }
        #pragma unroll 1
        for (int k = 0; k < BK2; k += 2) {
            float4 a4[12];
            #pragma unroll
            for (int p = 0; p < 12; p++)
                a4[p] = *(const float4*)&As2[(tm * 12 + p) * AST2 + k * 2];
            #pragma unroll
            for (int kk = 0; kk < 2; kk++) {
                const u64 b0 = *(const u64*)&Bs[(k + kk) * BN2 + tn * 2];
                const u64 b1 = *(const u64*)&Bs[(k + kk) * BN2 + 64 + tn * 2];
                #pragma unroll
                for (int p = 0; p < 12; p++) {
                    const u64 a2 = ((const u64*)&a4[p])[kk];
                    acc[p][0] = ffma2(a2, b0, acc[p][0]);
                    acc[p][1] = ffma2(a2, b1, acc[p][1]);
                }
            }
        }
    }
    #pragma unroll
    for (int p = 0; p < 12; p++) {
        const int r = r0 + tm * 12 + p;
        const float bias = g_bc[r];
        float* orow = &g_ker[((size_t)b * RROWS + r) * HW + n0];
        #pragma unroll
        for (int q = 0; q < 2; q++) {
            float2 v = unpack2(acc[p][q]);
            *(float2*)&orow[tn * 2 + 64 * q] = make_float2(v.x + bias, v.y + bias);
        }
    }
}

// ---------------- kernel fold: Kp = sum_ki shifted ker ---------------------
__global__ void fold_ker() {
    const int idx = blockIdx.x * 256 + threadIdx.x;   // < 1572864
    const int m  = idx & 63;
    const int i  = (idx >> 6) & 63;
    const int t  = idx >> 12;
    const int kj = t % 3;
    const int bg = t / 3;
    const int b  = bg >> 4, g = bg & 15;
    const float* base = g_ker + ((size_t)b * RROWS + g * KK) * HW + i * HWD;
    float v = base[(3 + kj) * HW + m];
    if (m < 63) v += base[(0 + kj) * HW + m + 1];
    if (m > 0)  v += base[(6 + kj) * HW + m - 1];
    g_Kp[idx] = v;
}

// ---------------- kernel C: main einsum, FFMA2 packed over channel pairs ---
// CTA: (b, g, cq) -> 4 channels = 2 channel-pairs. 256 thr, 8 warps.
// xsI[cp][m][t] = (x[c0][m][t-1], x[c1][m][t-1]), t in 0..65 (halo t=0,65)
// As2[i][m] duplicated pairs (v,v) of Kp[kj][i][m], staged per kj.
#define RS2 136              // floats per m-row (68 pairs)
#define CPS (64 * 136)       // 8704 floats per channel-pair plane
#define AST 132              // floats per i-row of As2 (64 m * 2 + pad)
#define XS_FLOATS (2 * CPS)
#define SMEM2_BYTES ((XS_FLOATS + 64 * AST) * 4)   // 103424

__global__ __launch_bounds__(256, 2) void inv_main2(const float* __restrict__ x,
                                                    float* __restrict__ out) {
    extern __shared__ float sm[];
    float* xs  = sm;
    float* As2 = sm + XS_FLOATS;

    const int cq = blockIdx.x;      // 0..3
    const int g  = blockIdx.y;
    const int b  = blockIdx.z;
    const int tid = threadIdx.x;
    const int ti  = tid >> 5;       // warp -> i block of 8
    const int tn  = tid & 31;       // lane -> j (and j+32)
    const int ch0 = g * 16 + cq * 4;
    const float* xb = x + ((size_t)b * CH + ch0) * HW;

    // zero halo pairs (t=0 -> floats 0,1 ; t=65 -> floats 130,131)
    {
        const int e = tid;                   // 256 = 2cp * 64m * 2h
        const int cp = e >> 7, r = e & 127, m = r >> 1, h = r & 1;
        *(u64*)&xs[cp * CPS + m * RS2 + h * 130] = 0ull;
    }
    // load x, channel-interleaved pairs
    #pragma unroll
    for (int it = 0; it < 16; it++) {
        const int e4 = tid + 256 * it;       // < 4096
        const int c  = e4 >> 10;
        const int rm = e4 & 1023;
        const int m  = rm >> 4, j4 = (rm & 15) << 2;
        float4 v = *(const float4*)&xb[(size_t)c * HW + m * HWD + j4];
        float* dst = &xs[(c >> 1) * CPS + m * RS2 + (j4 + 1) * 2 + (c & 1)];
        dst[0] = v.x; dst[2] = v.y; dst[4] = v.z; dst[6] = v.w;
    }

    u64 acc[8][4];
    #pragma unroll
    for (int p = 0; p < 8; p++)
        #pragma unroll
        for (int q = 0; q < 4; q++) acc[p][q] = 0ull;

    const float* Kpb = g_Kp + ((size_t)b * G_ + g) * 3 * HW;

    for (int kj = 0; kj < 3; kj++) {
        __syncthreads();
        // stage duplicated Kp[kj] tile
        #pragma unroll
        for (int it = 0; it < 4; it++) {
            const int e4 = tid + 256 * it;   // < 1024
            const int i = e4 >> 4, m4 = (e4 & 15) << 2;
            float4 v = *(const float4*)&Kpb[kj * HW + i * HWD + m4];
            u64* d = (u64*)&As2[i * AST + m4 * 2];
            d[0] = pack2(v.x, v.x); d[1] = pack2(v.y, v.y);
            d[2] = pack2(v.z, v.z); d[3] = pack2(v.w, v.w);
        }
        __syncthreads();

        #pragma unroll 1
        for (int m2 = 0; m2 < 64; m2 += 2) {
            float4 a4[8];
            #pragma unroll
            for (int p = 0; p < 8; p++)
                a4[p] = *(const float4*)&As2[(ti * 8 + p) * AST + m2 * 2];
            #pragma unroll
            for (int mm = 0; mm < 2; mm++) {
                const float* xr = xs + (m2 + mm) * RS2 + kj * 2 + tn * 2;
                const u64 b0 = *(const u64*)(xr);
                const u64 b1 = *(const u64*)(xr + 64);
                const u64 b2 = *(const u64*)(xr + CPS);
                const u64 b3 = *(const u64*)(xr + CPS + 64);
                #pragma unroll
                for (int p = 0; p < 8; p++) {
                    const u64 a2 = ((const u64*)&a4[p])[mm];
                    acc[p][0] = ffma2(a2, b0, acc[p][0]);
                    acc[p][1] = ffma2(a2, b1, acc[p][1]);
                    acc[p][2] = ffma2(a2, b2, acc[p][2]);
                    acc[p][3] = ffma2(a2, b3, acc[p][3]);
                }
            }
        }
    }

    // epilogue: lo lane -> channel chA, hi lane -> chA+1
    #pragma unroll
    for (int p = 0; p < 8; p++) {
        const int i = ti * 8 + p;
        #pragma unroll
        for (int q = 0; q < 4; q++) {
            float2 v = unpack2(acc[p][q]);
            const int chA = ch0 + (q >> 1) * 2;
            const int j = tn + (q & 1) * 32;
            out[(((size_t)b * CH + chA)     * HWD + i) * HWD + j] = v.x;
            out[(((size_t)b * CH + chA + 1) * HWD + i) * HWD + j] = v.y;
        }
    }
}

// ---------------- launch ----------------------------------------------------
extern "C" void kernel_launch(void* const* d_in, const int* in_sizes, int n_in,
                              void* d_out, int out_size) {
    const float* x        = (const float*)d_in[0];
    const float* W_reduce = (const float*)d_in[1];
    const float* b_reduce = (const float*)d_in[2];
    const float* W_span   = (const float*)d_in[3];
    const float* b_span   = (const float*)d_in[4];
    float* out = (float*)d_out;

    cudaFuncSetAttribute(inv_main2, cudaFuncAttributeMaxDynamicSharedMemorySize, SMEM2_BYTES);

    fuse_weights<<<RROWS, 128>>>(W_reduce, b_reduce, W_span, b_span);
    ker_gemm2<<<dim3(HW / BN2, RROWS / BM2, B_), 128>>>(x);
    fold_ker<<<(B_ * G_ * 3 * HW) / 256, 256>>>();
    inv_main2<<<dim3(4, G_, B_), 256, SMEM2_BYTES>>>(x, out);
}

// round 3
// speedup vs baseline: 1.4621x; 1.0271x over previous
#include <cuda_runtime.h>

typedef unsigned long long u64;

// Problem constants
#define CH      256
#define G_      16
#define KK      9
#define RROWS   144
#define RED_CH  128
#define B_      8
#define HWD     64
#define HW      4096

// ---------------- f32x2 helpers --------------------------------------------
__device__ __forceinline__ u64 ffma2(u64 a, u64 b, u64 c) {
    u64 d;
    asm("fma.rn.f32x2 %0, %1, %2, %3;" : "=l"(d) : "l"(a), "l"(b), "l"(c));
    return d;
}
__device__ __forceinline__ u64 pack2(float lo, float hi) {
    u64 d; asm("mov.b64 %0, {%1, %2};" : "=l"(d) : "f"(lo), "f"(hi)); return d;
}
__device__ __forceinline__ float2 unpack2(u64 v) {
    float2 r; asm("mov.b64 {%0, %1}, %2;" : "=f"(r.x), "=f"(r.y) : "l"(v)); return r;
}

// ---------------- device scratch -------------------------------------------
__device__ float g_Wc[RROWS * CH];
__device__ float g_bc[RROWS];
__device__ float g_ker[B_ * RROWS * HW];
__device__ float g_Kp[B_ * G_ * 3 * HW];

// ---------------- kernel A: fuse weights -----------------------------------
__global__ void fuse_weights(const float* __restrict__ W_reduce,
                             const float* __restrict__ b_reduce,
                             const float* __restrict__ W_span,
                             const float* __restrict__ b_span) {
    __shared__ float ws[RED_CH];
    const int r = blockIdx.x;
    const int t = threadIdx.x;          // 128
    ws[t] = W_span[r * RED_CH + t];
    __syncthreads();
    #pragma unroll
    for (int cc = 0; cc < 2; cc++) {
        const int c = t + cc * 128;
        float s = 0.f;
        #pragma unroll 8
        for (int o = 0; o < RED_CH; o++) s += ws[o] * W_reduce[o * CH + c];
        g_Wc[r * CH + c] = s;
    }
    if (t == 0) {
        float s = 0.f;
        for (int o = 0; o < RED_CH; o++) s += ws[o] * b_reduce[o];
        g_bc[r] = s + b_span[r];
    }
}

// ---------------- kernel B: ker = Wc @ x, FFMA2, double-buffered -----------
// 256 threads. BM=48 (all of a 48-row band), BN=256 floats, BK=16.
// Thread tile 12(r) x 2(u64 n-pairs). One __syncthreads per k-tile.
#define BK3   16
#define BN3   256
#define AST3  36          // floats per r-row of dup-pair A tile (16k*2 + pad)
#define NT3   16          // K / BK3

__global__ __launch_bounds__(256, 2) void ker_gemm3(const float* __restrict__ x) {
    __shared__ float As2[2][48 * AST3];   // 2 x 6.75 KB (dup pairs)
    __shared__ float Bs[2][BK3 * BN3];    // 2 x 16 KB
    const int b  = blockIdx.z;
    const int r0 = blockIdx.y * 48;
    const int n0 = blockIdx.x * BN3;
    const int tid = threadIdx.x;
    const int tm  = tid >> 6;             // 0..3  -> r block of 12
    const int tn  = tid & 63;             // 0..63 -> n pair
    const float* xb = x + (size_t)b * CH * HW;

    float  areg[3];
    float4 breg[4];

    // load tile 0 into regs
    #pragma unroll
    for (int it = 0; it < 3; it++) {
        const int e = tid + 256 * it, r = e >> 4, k = e & 15;
        areg[it] = g_Wc[(r0 + r) * CH + k];
    }
    #pragma unroll
    for (int it = 0; it < 4; it++) {
        const int e4 = tid + 256 * it, k = e4 >> 6, n4 = (e4 & 63) * 4;
        breg[it] = *(const float4*)&xb[(size_t)k * HW + n0 + n4];
    }

    u64 acc[12][2];
    #pragma unroll
    for (int p = 0; p < 12; p++) { acc[p][0] = 0ull; acc[p][1] = 0ull; }

    #pragma unroll 1
    for (int t = 0; t < NT3; t++) {
        const int buf = t & 1;
        // store staged regs
        #pragma unroll
        for (int it = 0; it < 3; it++) {
            const int e = tid + 256 * it, r = e >> 4, k = e & 15;
            *(u64*)&As2[buf][r * AST3 + k * 2] = pack2(areg[it], areg[it]);
        }
        #pragma unroll
        for (int it = 0; it < 4; it++) {
            const int e4 = tid + 256 * it, k = e4 >> 6, n4 = (e4 & 63) * 4;
            *(float4*)&Bs[buf][k * BN3 + n4] = breg[it];
        }
        __syncthreads();
        // prefetch next tile
        if (t + 1 < NT3) {
            const int kn = (t + 1) * BK3;
            #pragma unroll
            for (int it = 0; it < 3; it++) {
                const int e = tid + 256 * it, r = e >> 4, k = e & 15;
                areg[it] = g_Wc[(r0 + r) * CH + kn + k];
            }
            #pragma unroll
            for (int it = 0; it < 4; it++) {
                const int e4 = tid + 256 * it, k = e4 >> 6, n4 = (e4 & 63) * 4;
                breg[it] = *(const float4*)&xb[(size_t)(kn + k) * HW + n0 + n4];
            }
        }
        // compute on buf
        #pragma unroll
        for (int k = 0; k < BK3; k += 2) {
            float4 a4[12];
            #pragma unroll
            for (int p = 0; p < 12; p++)
                a4[p] = *(const float4*)&As2[buf][(tm * 12 + p) * AST3 + k * 2];
            #pragma unroll
            for (int kk = 0; kk < 2; kk++) {
                const u64 b0 = *(const u64*)&Bs[buf][(k + kk) * BN3 + tn * 2];
                const u64 b1 = *(const u64*)&Bs[buf][(k + kk) * BN3 + 128 + tn * 2];
                #pragma unroll
                for (int p = 0; p < 12; p++) {
                    const u64 a2 = ((const u64*)&a4[p])[kk];
                    acc[p][0] = ffma2(a2, b0, acc[p][0]);
                    acc[p][1] = ffma2(a2, b1, acc[p][1]);
                }
            }
        }
    }
    #pragma unroll
    for (int p = 0; p < 12; p++) {
        const int r = r0 + tm * 12 + p;
        const float bias = g_bc[r];
        float* orow = &g_ker[((size_t)b * RROWS + r) * HW + n0];
        #pragma unroll
        for (int q = 0; q < 2; q++) {
            float2 v = unpack2(acc[p][q]);
            *(float2*)&orow[tn * 2 + 128 * q] = make_float2(v.x + bias, v.y + bias);
        }
    }
}

// ---------------- kernel fold ----------------------------------------------
__global__ void fold_ker() {
    const int idx = blockIdx.x * 256 + threadIdx.x;
    const int m  = idx & 63;
    const int i  = (idx >> 6) & 63;
    const int t  = idx >> 12;
    const int kj = t % 3;
    const int bg = t / 3;
    const int b  = bg >> 4, g = bg & 15;
    const float* base = g_ker + ((size_t)b * RROWS + g * KK) * HW + i * HWD;
    float v = base[(3 + kj) * HW + m];
    if (m < 63) v += base[(0 + kj) * HW + m + 1];
    if (m > 0)  v += base[(6 + kj) * HW + m - 1];
    g_Kp[idx] = v;
}

// ---------------- kernel C: main einsum, b-operand software pipeline -------
#define RS2 136
#define CPS (64 * 136)
#define AST 132
#define XS_FLOATS (2 * CPS)
#define SMEM2_BYTES ((XS_FLOATS + 64 * AST) * 4)   // 103424

__global__ __launch_bounds__(256, 2) void inv_main3(const float* __restrict__ x,
                                                    float* __restrict__ out) {
    extern __shared__ float sm[];
    float* xs  = sm;
    float* As2 = sm + XS_FLOATS;

    const int cq = blockIdx.x;
    const int g  = blockIdx.y;
    const int b  = blockIdx.z;
    const int tid = threadIdx.x;
    const int ti  = tid >> 5;
    const int tn  = tid & 31;
    const int ch0 = g * 16 + cq * 4;
    const float* xb = x + ((size_t)b * CH + ch0) * HW;

    // zero halo pairs
    {
        const int e = tid;
        const int cp = e >> 7, r = e & 127, m = r >> 1, h = r & 1;
        *(u64*)&xs[cp * CPS + m * RS2 + h * 130] = 0ull;
    }
    // load x channel-interleaved pairs
    #pragma unroll
    for (int it = 0; it < 16; it++) {
        const int e4 = tid + 256 * it;
        const int c  = e4 >> 10;
        const int rm = e4 & 1023;
        const int m  = rm >> 4, j4 = (rm & 15) << 2;
        float4 v = *(const float4*)&xb[(size_t)c * HW + m * HWD + j4];
        float* dst = &xs[(c >> 1) * CPS + m * RS2 + (j4 + 1) * 2 + (c & 1)];
        dst[0] = v.x; dst[2] = v.y; dst[4] = v.z; dst[6] = v.w;
    }

    u64 acc[8][4];
    #pragma unroll
    for (int p = 0; p < 8; p++)
        #pragma unroll
        for (int q = 0; q < 4; q++) acc[p][q] = 0ull;

    const float* Kpb = g_Kp + ((size_t)b * G_ + g) * 3 * HW;

    for (int kj = 0; kj < 3; kj++) {
        __syncthreads();
        #pragma unroll
        for (int it = 0; it < 4; it++) {
            const int e4 = tid + 256 * it;
            const int i = e4 >> 4, m4 = (e4 & 15) << 2;
            float4 v = *(const float4*)&Kpb[kj * HW + i * HWD + m4];
            u64* d = (u64*)&As2[i * AST + m4 * 2];
            d[0] = pack2(v.x, v.x); d[1] = pack2(v.y, v.y);
            d[2] = pack2(v.z, v.z); d[3] = pack2(v.w, v.w);
        }
        __syncthreads();

        const float* xbase = xs + kj * 2 + tn * 2;
        const float* arow  = As2 + (ti * 8) * AST;

        // software pipeline: bA holds b(m), prefetch b(m+1), b(m+2)
        u64 bA[4];
        bA[0] = *(const u64*)(xbase);
        bA[1] = *(const u64*)(xbase + 64);
        bA[2] = *(const u64*)(xbase + CPS);
        bA[3] = *(const u64*)(xbase + CPS + 64);

        #pragma unroll 1
        for (int m2 = 0; m2 < 64; m2 += 2) {
            float4 a4[8];
            #pragma unroll
            for (int p = 0; p < 8; p++)
                a4[p] = *(const float4*)&arow[p * AST + m2 * 2];

            const float* xr1 = xbase + (m2 + 1) * RS2;
            u64 bB[4];
            bB[0] = *(const u64*)(xr1);
            bB[1] = *(const u64*)(xr1 + 64);
            bB[2] = *(const u64*)(xr1 + CPS);
            bB[3] = *(const u64*)(xr1 + CPS + 64);

            #pragma unroll
            for (int p = 0; p < 8; p++) {
                const u64 a2 = ((const u64*)&a4[p])[0];
                acc[p][0] = ffma2(a2, bA[0], acc[p][0]);
                acc[p][1] = ffma2(a2, bA[1], acc[p][1]);
                acc[p][2] = ffma2(a2, bA[2], acc[p][2]);
                acc[p][3] = ffma2(a2, bA[3], acc[p][3]);
            }

            const float* xr2 = xbase + ((m2 + 2) & 63) * RS2;   // clamped dummy on last iter
            bA[0] = *(const u64*)(xr2);
            bA[1] = *(const u64*)(xr2 + 64);
            bA[2] = *(const u64*)(xr2 + CPS);
            bA[3] = *(const u64*)(xr2 + CPS + 64);

            #pragma unroll
            for (int p = 0; p < 8; p++) {
                const u64 a2 = ((const u64*)&a4[p])[1];
                acc[p][0] = ffma2(a2, bB[0], acc[p][0]);
                acc[p][1] = ffma2(a2, bB[1], acc[p][1]);
                acc[p][2] = ffma2(a2, bB[2], acc[p][2]);
                acc[p][3] = ffma2(a2, bB[3], acc[p][3]);
            }
        }
    }

    // epilogue
    #pragma unroll
    for (int p = 0; p < 8; p++) {
        const int i = ti * 8 + p;
        #pragma unroll
        for (int q = 0; q < 4; q++) {
            float2 v = unpack2(acc[p][q]);
            const int chA = ch0 + (q >> 1) * 2;
            const int j = tn + (q & 1) * 32;
            out[(((size_t)b * CH + chA)     * HWD + i) * HWD + j] = v.x;
            out[(((size_t)b * CH + chA + 1) * HWD + i) * HWD + j] = v.y;
        }
    }
}

// ---------------- launch ----------------------------------------------------
extern "C" void kernel_launch(void* const* d_in, const int* in_sizes, int n_in,
                              void* d_out, int out_size) {
    const float* x        = (const float*)d_in[0];
    const float* W_reduce = (const float*)d_in[1];
    const float* b_reduce = (const float*)d_in[2];
    const float* W_span   = (const float*)d_in[3];
    const float* b_span   = (const float*)d_in[4];
    float* out = (float*)d_out;

    cudaFuncSetAttribute(inv_main3, cudaFuncAttributeMaxDynamicSharedMemorySize, SMEM2_BYTES);

    fuse_weights<<<RROWS, 128>>>(W_reduce, b_reduce, W_span, b_span);
    ker_gemm3<<<dim3(HW / BN3, RROWS / 48, B_), 256>>>(x);
    fold_ker<<<(B_ * G_ * 3 * HW) / 256, 256>>>();
    inv_main3<<<dim3(4, G_, B_), 256, SMEM2_BYTES>>>(x, out);
}

// round 5
// speedup vs baseline: 1.9905x; 1.3614x over previous
#include <cuda_runtime.h>
#include <cuda_bf16.h>
#include <cstdint>

typedef unsigned long long u64;

// Problem constants
#define CH      256
#define G_      16
#define KK      9
#define RROWS   144
#define RED_CH  128
#define B_      8
#define HWD     64
#define HW      4096

// ---------------- f32x2 helpers (ker_gemm3) ---------------------------------
__device__ __forceinline__ u64 ffma2(u64 a, u64 b, u64 c) {
    u64 d;
    asm("fma.rn.f32x2 %0, %1, %2, %3;" : "=l"(d) : "l"(a), "l"(b), "l"(c));
    return d;
}
__device__ __forceinline__ u64 pack2(float lo, float hi) {
    u64 d; asm("mov.b64 %0, {%1, %2};" : "=l"(d) : "f"(lo), "f"(hi)); return d;
}
__device__ __forceinline__ float2 unpack2(u64 v) {
    float2 r; asm("mov.b64 {%0, %1}, %2;" : "=f"(r.x), "=f"(r.y) : "l"(v)); return r;
}

// ---------------- mma.sync helpers (sm_80+, compiles for plain sm_103) ------
__device__ __forceinline__ uint32_t smem_u32(const void* p) {
    uint32_t a;
    asm("{ .reg .u64 t; cvta.to.shared.u64 t, %1; cvt.u32.u64 %0, t; }" : "=r"(a) : "l"(p));
    return a;
}
__device__ __forceinline__ void ldm_x4(uint32_t& r0, uint32_t& r1, uint32_t& r2,
                                       uint32_t& r3, uint32_t addr) {
    asm volatile("ldmatrix.sync.aligned.m8n8.x4.shared.b16 {%0,%1,%2,%3}, [%4];"
        : "=r"(r0), "=r"(r1), "=r"(r2), "=r"(r3) : "r"(addr));
}
__device__ __forceinline__ void ldm_x2t(uint32_t& r0, uint32_t& r1, uint32_t addr) {
    asm volatile("ldmatrix.sync.aligned.m8n8.x2.trans.shared.b16 {%0,%1}, [%2];"
        : "=r"(r0), "=r"(r1) : "r"(addr));
}
__device__ __forceinline__ void mma_bf16(float* c, const uint32_t* a, const uint32_t* b) {
    asm volatile("mma.sync.aligned.m16n8k16.row.col.f32.bf16.bf16.f32 "
        "{%0,%1,%2,%3}, {%4,%5,%6,%7}, {%8,%9}, {%0,%1,%2,%3};"
        : "+f"(c[0]), "+f"(c[1]), "+f"(c[2]), "+f"(c[3])
        : "r"(a[0]), "r"(a[1]), "r"(a[2]), "r"(a[3]), "r"(b[0]), "r"(b[1]));
}
// bf16 hi/lo split of two floats, packed as bf16x2 words
__device__ __forceinline__ void bsplit2(float a, float b, uint32_t& hi, uint32_t& lo) {
    __nv_bfloat162 h = __floats2bfloat162_rn(a, b);
    hi = *reinterpret_cast<uint32_t*>(&h);
    float ra = a - __bfloat162float(h.x);
    float rb = b - __bfloat162float(h.y);
    __nv_bfloat162 l = __floats2bfloat162_rn(ra, rb);
    lo = *reinterpret_cast<uint32_t*>(&l);
}

// ---------------- device scratch -------------------------------------------
__device__ float g_Wc[RROWS * CH];
__device__ float g_bc[RROWS];
__device__ float g_ker[B_ * RROWS * HW];
__device__ float g_Kp[B_ * G_ * 3 * HW];

// ---------------- kernel A: fuse weights -----------------------------------
__global__ void fuse_weights(const float* __restrict__ W_reduce,
                             const float* __restrict__ b_reduce,
                             const float* __restrict__ W_span,
                             const float* __restrict__ b_span) {
    __shared__ float ws[RED_CH];
    const int r = blockIdx.x;
    const int t = threadIdx.x;          // 128
    ws[t] = W_span[r * RED_CH + t];
    __syncthreads();
    #pragma unroll
    for (int cc = 0; cc < 2; cc++) {
        const int c = t + cc * 128;
        float s = 0.f;
        #pragma unroll 8
        for (int o = 0; o < RED_CH; o++) s += ws[o] * W_reduce[o * CH + c];
        g_Wc[r * CH + c] = s;
    }
    if (t == 0) {
        float s = 0.f;
        for (int o = 0; o < RED_CH; o++) s += ws[o] * b_reduce[o];
        g_bc[r] = s + b_span[r];
    }
}

// ---------------- kernel B: ker = Wc @ x (unchanged, FFMA2) -----------------
#define BK3   16
#define BN3   256
#define AST3  36
#define NT3   16

__global__ __launch_bounds__(256, 2) void ker_gemm3(const float* __restrict__ x) {
    __shared__ float As2[2][48 * AST3];
    __shared__ float Bs[2][BK3 * BN3];
    const int b  = blockIdx.z;
    const int r0 = blockIdx.y * 48;
    const int n0 = blockIdx.x * BN3;
    const int tid = threadIdx.x;
    const int tm  = tid >> 6;
    const int tn  = tid & 63;
    const float* xb = x + (size_t)b * CH * HW;

    float  areg[3];
    float4 breg[4];
    #pragma unroll
    for (int it = 0; it < 3; it++) {
        const int e = tid + 256 * it, r = e >> 4, k = e & 15;
        areg[it] = g_Wc[(r0 + r) * CH + k];
    }
    #pragma unroll
    for (int it = 0; it < 4; it++) {
        const int e4 = tid + 256 * it, k = e4 >> 6, n4 = (e4 & 63) * 4;
        breg[it] = *(const float4*)&xb[(size_t)k * HW + n0 + n4];
    }

    u64 acc[12][2];
    #pragma unroll
    for (int p = 0; p < 12; p++) { acc[p][0] = 0ull; acc[p][1] = 0ull; }

    #pragma unroll 1
    for (int t = 0; t < NT3; t++) {
        const int buf = t & 1;
        #pragma unroll
        for (int it = 0; it < 3; it++) {
            const int e = tid + 256 * it, r = e >> 4, k = e & 15;
            *(u64*)&As2[buf][r * AST3 + k * 2] = pack2(areg[it], areg[it]);
        }
        #pragma unroll
        for (int it = 0; it < 4; it++) {
            const int e4 = tid + 256 * it, k = e4 >> 6, n4 = (e4 & 63) * 4;
            *(float4*)&Bs[buf][k * BN3 + n4] = breg[it];
        }
        __syncthreads();
        if (t + 1 < NT3) {
            const int kn = (t + 1) * BK3;
            #pragma unroll
            for (int it = 0; it < 3; it++) {
                const int e = tid + 256 * it, r = e >> 4, k = e & 15;
                areg[it] = g_Wc[(r0 + r) * CH + kn + k];
            }
            #pragma unroll
            for (int it = 0; it < 4; it++) {
                const int e4 = tid + 256 * it, k = e4 >> 6, n4 = (e4 & 63) * 4;
                breg[it] = *(const float4*)&xb[(size_t)(kn + k) * HW + n0 + n4];
            }
        }
        #pragma unroll
        for (int k = 0; k < BK3; k += 2) {
            float4 a4[12];
            #pragma unroll
            for (int p = 0; p < 12; p++)
                a4[p] = *(const float4*)&As2[buf][(tm * 12 + p) * AST3 + k * 2];
            #pragma unroll
            for (int kk = 0; kk < 2; kk++) {
                const u64 b0 = *(const u64*)&Bs[buf][(k + kk) * BN3 + tn * 2];
                const u64 b1 = *(const u64*)&Bs[buf][(k + kk) * BN3 + 128 + tn * 2];
                #pragma unroll
                for (int p = 0; p < 12; p++) {
                    const u64 a2 = ((const u64*)&a4[p])[kk];
                    acc[p][0] = ffma2(a2, b0, acc[p][0]);
                    acc[p][1] = ffma2(a2, b1, acc[p][1]);
                }
            }
        }
    }
    #pragma unroll
    for (int p = 0; p < 12; p++) {
        const int r = r0 + tm * 12 + p;
        const float bias = g_bc[r];
        float* orow = &g_ker[((size_t)b * RROWS + r) * HW + n0];
        #pragma unroll
        for (int q = 0; q < 2; q++) {
            float2 v = unpack2(acc[p][q]);
            *(float2*)&orow[tn * 2 + 128 * q] = make_float2(v.x + bias, v.y + bias);
        }
    }
}

// ---------------- kernel fold ------------------------------------------------
__global__ void fold_ker() {
    const int idx = blockIdx.x * 256 + threadIdx.x;
    const int m  = idx & 63;
    const int i  = (idx >> 6) & 63;
    const int t  = idx >> 12;
    const int kj = t % 3;
    const int bg = t / 3;
    const int b  = bg >> 4, g = bg & 15;
    const float* base = g_ker + ((size_t)b * RROWS + g * KK) * HW + i * HWD;
    float v = base[(3 + kj) * HW + m];
    if (m < 63) v += base[(0 + kj) * HW + m + 1];
    if (m > 0)  v += base[(6 + kj) * HW + m - 1];
    g_Kp[idx] = v;
}

// ---------------- kernel C: mma.sync bf16-split main einsum ------------------
// CTA = (c, g, b). D[192=(3kj x 64i)][64j] = Kp(A, row-major) @ x[c](B, [m][j]).
// bf16 split, 3 passes. Epilogue: out[i][j] = Y0[i][j-1] + Y1[i][j] + Y2[i][j+1].
#define A_STRB  144        // bytes per bf16 row (72 bf16: 64 data + 8 pad)
#define OFF_AH  0
#define OFF_AL  27648      // 192*144
#define OFF_BH  55296
#define OFF_BL  64512      // +64*144
#define SMEM_MMA 73728
#define YSTR    68         // fp32 Y row stride (floats)

__global__ __launch_bounds__(256, 2) void inv_mma(const float* __restrict__ x,
                                                  float* __restrict__ out) {
    extern __shared__ char smem[];
    const uint32_t sb = smem_u32(smem);
    const int c = blockIdx.x, g = blockIdx.y, b = blockIdx.z;
    const int tid  = threadIdx.x;
    const int wid  = tid >> 5, lane = tid & 31;
    const int wm   = wid & 3;          // M quadrant (48 rows)
    const int wn   = wid >> 2;         // N half (32 cols)

    // ---- convert A = Kp[b][g] (192 x 64 fp32, native row-major) -> bf16 hi/lo
    const float* Kpb = g_Kp + ((size_t)(b * G_ + g)) * 3 * HW;
    #pragma unroll
    for (int it = 0; it < 12; it++) {
        const int e4 = tid + 256 * it;             // < 3072
        const int row = e4 >> 4, q = (e4 & 15) << 2;
        float4 v = *(const float4*)&Kpb[row * 64 + q];
        uint32_t h0, l0, h1, l1;
        bsplit2(v.x, v.y, h0, l0);
        bsplit2(v.z, v.w, h1, l1);
        const uint32_t off = row * A_STRB + q * 2;
        *(uint2*)(smem + OFF_AH + off) = make_uint2(h0, h1);
        *(uint2*)(smem + OFF_AL + off) = make_uint2(l0, l1);
    }
    // ---- convert B = x[c] (64m x 64j, native row-major) -> bf16 hi/lo -------
    const float* xc = x + ((size_t)(b * CH) + g * 16 + c) * HW;
    #pragma unroll
    for (int it = 0; it < 4; it++) {
        const int e4 = tid + 256 * it;             // < 1024
        const int row = e4 >> 4, q = (e4 & 15) << 2;
        float4 v = *(const float4*)&xc[row * 64 + q];
        uint32_t h0, l0, h1, l1;
        bsplit2(v.x, v.y, h0, l0);
        bsplit2(v.z, v.w, h1, l1);
        const uint32_t off = row * A_STRB + q * 2;
        *(uint2*)(smem + OFF_BH + off) = make_uint2(h0, h1);
        *(uint2*)(smem + OFF_BL + off) = make_uint2(l0, l1);
    }
    __syncthreads();

    float acc[3][4][4];
    #pragma unroll
    for (int mt = 0; mt < 3; mt++)
        #pragma unroll
        for (int nt = 0; nt < 4; nt++)
            #pragma unroll
            for (int e = 0; e < 4; e++) acc[mt][nt][e] = 0.f;

    const int r  = lane & 15;
    const int hh = lane >> 4;
    #pragma unroll
    for (int k = 0; k < 4; k++) {
        uint32_t ah[3][4], al[3][4], bh[4][2], bl[4][2];
        #pragma unroll
        for (int mt = 0; mt < 3; mt++) {
            const uint32_t base = sb + (wm * 48 + mt * 16 + r) * A_STRB + k * 32 + hh * 16;
            ldm_x4(ah[mt][0], ah[mt][1], ah[mt][2], ah[mt][3], base + OFF_AH);
            ldm_x4(al[mt][0], al[mt][1], al[mt][2], al[mt][3], base + OFF_AL);
        }
        #pragma unroll
        for (int nt = 0; nt < 4; nt++) {
            const uint32_t base = sb + (k * 16 + r) * A_STRB + (wn * 32 + nt * 8) * 2;
            ldm_x2t(bh[nt][0], bh[nt][1], base + OFF_BH);
            ldm_x2t(bl[nt][0], bl[nt][1], base + OFF_BL);
        }
        #pragma unroll
        for (int mt = 0; mt < 3; mt++)
            #pragma unroll
            for (int nt = 0; nt < 4; nt++) {
                mma_bf16(acc[mt][nt], ah[mt], bh[nt]);
                mma_bf16(acc[mt][nt], ah[mt], bl[nt]);
                mma_bf16(acc[mt][nt], al[mt], bh[nt]);
            }
    }

    // ---- spill Y (192 x 64 fp32) to smem, reusing the dead A region ---------
    __syncthreads();
    float* Ys = (float*)smem;
    const int gq = lane >> 2, cb = (lane & 3) * 2;
    #pragma unroll
    for (int mt = 0; mt < 3; mt++)
        #pragma unroll
        for (int nt = 0; nt < 4; nt++) {
            const int row = wm * 48 + mt * 16 + gq;
            const int col = wn * 32 + nt * 8 + cb;
            *(float2*)&Ys[row * YSTR + col]       = make_float2(acc[mt][nt][0], acc[mt][nt][1]);
            *(float2*)&Ys[(row + 8) * YSTR + col] = make_float2(acc[mt][nt][2], acc[mt][nt][3]);
        }
    __syncthreads();

    // ---- combine shifted rows, coalesced float4 stores ----------------------
    const int i  = tid >> 2;
    const int jb = (tid & 3) * 16;
    float* op = out + (((size_t)b * CH + g * 16 + c) * HWD + i) * HWD;
    const float* y0 = Ys + i * YSTR;
    const float* y1 = Ys + (64 + i) * YSTR;
    const float* y2 = Ys + (128 + i) * YSTR;
    #pragma unroll
    for (int u = 0; u < 4; u++) {
        const int j0 = jb + u * 4;
        float vals[4];
        #pragma unroll
        for (int e = 0; e < 4; e++) {
            const int j = j0 + e;
            float v = y1[j];
            if (j > 0)  v += y0[j - 1];
            if (j < 63) v += y2[j + 1];
            vals[e] = v;
        }
        *(float4*)&op[j0] = make_float4(vals[0], vals[1], vals[2], vals[3]);
    }
}

// ---------------- launch ------------------------------------------------------
extern "C" void kernel_launch(void* const* d_in, const int* in_sizes, int n_in,
                              void* d_out, int out_size) {
    const float* x        = (const float*)d_in[0];
    const float* W_reduce = (const float*)d_in[1];
    const float* b_reduce = (const float*)d_in[2];
    const float* W_span   = (const float*)d_in[3];
    const float* b_span   = (const float*)d_in[4];
    float* out = (float*)d_out;

    cudaFuncSetAttribute(inv_mma, cudaFuncAttributeMaxDynamicSharedMemorySize, SMEM_MMA);

    fuse_weights<<<RROWS, 128>>>(W_reduce, b_reduce, W_span, b_span);
    ker_gemm3<<<dim3(HW / BN3, RROWS / 48, B_), 256>>>(x);
    fold_ker<<<(B_ * G_ * 3 * HW) / 256, 256>>>();
    inv_mma<<<dim3(16, G_, B_), 256, SMEM_MMA>>>(x, out);
}

// round 6
// speedup vs baseline: 3.1837x; 1.5994x over previous
#include <cuda_runtime.h>
#include <cuda_bf16.h>
#include <cstdint>

// Problem constants
#define CH      256
#define G_      16
#define RROWS   144
#define RED_CH  128
#define B_      8
#define HWD     64
#define HW      4096

// ---------------- mma.sync helpers (sm_80+, plain sm_103 OK) ----------------
__device__ __forceinline__ uint32_t smem_u32(const void* p) {
    uint32_t a;
    asm("{ .reg .u64 t; cvta.to.shared.u64 t, %1; cvt.u32.u64 %0, t; }" : "=r"(a) : "l"(p));
    return a;
}
__device__ __forceinline__ void ldm_x4(uint32_t& r0, uint32_t& r1, uint32_t& r2,
                                       uint32_t& r3, uint32_t addr) {
    asm volatile("ldmatrix.sync.aligned.m8n8.x4.shared.b16 {%0,%1,%2,%3}, [%4];"
        : "=r"(r0), "=r"(r1), "=r"(r2), "=r"(r3) : "r"(addr));
}
__device__ __forceinline__ void ldm_x2t(uint32_t& r0, uint32_t& r1, uint32_t addr) {
    asm volatile("ldmatrix.sync.aligned.m8n8.x2.trans.shared.b16 {%0,%1}, [%2];"
        : "=r"(r0), "=r"(r1) : "r"(addr));
}
__device__ __forceinline__ void mma_bf16(float* c, const uint32_t* a, const uint32_t* b) {
    asm volatile("mma.sync.aligned.m16n8k16.row.col.f32.bf16.bf16.f32 "
        "{%0,%1,%2,%3}, {%4,%5,%6,%7}, {%8,%9}, {%0,%1,%2,%3};"
        : "+f"(c[0]), "+f"(c[1]), "+f"(c[2]), "+f"(c[3])
        : "r"(a[0]), "r"(a[1]), "r"(a[2]), "r"(a[3]), "r"(b[0]), "r"(b[1]));
}
__device__ __forceinline__ void bsplit2(float a, float b, uint32_t& hi, uint32_t& lo) {
    __nv_bfloat162 h = __floats2bfloat162_rn(a, b);
    hi = *reinterpret_cast<uint32_t*>(&h);
    float ra = a - __bfloat162float(h.x);
    float rb = b - __bfloat162float(h.y);
    __nv_bfloat162 l = __floats2bfloat162_rn(ra, rb);
    lo = *reinterpret_cast<uint32_t*>(&l);
}

// ---------------- device scratch (pre-split bf16) ----------------------------
__device__ uint4 g_WcH4[RROWS * 32];          // 144 x 256 bf16 (32 uint4/row)
__device__ uint4 g_WcL4[RROWS * 32];
__device__ uint4 g_KpH4[B_ * G_ * 192 * 9];   // per (b,g): 192 rows x 144B
__device__ uint4 g_KpL4[B_ * G_ * 192 * 9];
__device__ float g_bc[RROWS];

// ---------------- kernel A: fuse weights -> pre-split bf16 -------------------
__global__ void fuse_weights(const float* __restrict__ W_reduce,
                             const float* __restrict__ b_reduce,
                             const float* __restrict__ W_span,
                             const float* __restrict__ b_span) {
    __shared__ float ws[RED_CH];
    const int r = blockIdx.x;
    const int t = threadIdx.x;          // 128
    ws[t] = W_span[r * RED_CH + t];
    __syncthreads();
    const int c0 = t * 2;
    float s0 = 0.f, s1 = 0.f;
    #pragma unroll 8
    for (int o = 0; o < RED_CH; o++) {
        const float w = ws[o];
        s0 += w * W_reduce[o * CH + c0];
        s1 += w * W_reduce[o * CH + c0 + 1];
    }
    uint32_t hi, lo;
    bsplit2(s0, s1, hi, lo);
    ((uint32_t*)g_WcH4)[r * 128 + t] = hi;
    ((uint32_t*)g_WcL4)[r * 128 + t] = lo;
    if (t == 0) {
        float s = 0.f;
        for (int o = 0; o < RED_CH; o++) s += ws[o] * b_reduce[o];
        g_bc[r] = s + b_span[r];
    }
}

// ---------------- kernel B: ker GEMM + fold, tensorized ----------------------
// CTA = (image row i0, b). D[144 r][64 m] = Wc @ x[b][:, i0, :], K=256 (4 tiles).
// Epilogue: fold over ki (shift along m) + bias, write pre-split bf16 Kp.
#define KSTR   144          // smem row stride (bytes): 64 bf16 + 16 pad
#define KF_AH  0
#define KF_AL  20736        // 144*144
#define KF_BH  41472
#define KF_BL  50688        // +64*144
#define KF_BC  59904
#define KF_SMEM (KF_BC + 576)

__global__ __launch_bounds__(256, 2) void ker_fold(const float* __restrict__ x) {
    extern __shared__ char smem[];
    const uint32_t sb = smem_u32(smem);
    float* sbc = (float*)(smem + KF_BC);
    const int i0 = blockIdx.x;          // 0..63
    const int b  = blockIdx.y;
    const int tid = threadIdx.x;
    const int wid = tid >> 5, lane = tid & 31;
    const int r  = lane & 15, hh = lane >> 4;

    if (tid < RROWS) sbc[tid] = g_bc[tid];

    float acc[9][4];
    #pragma unroll
    for (int mt = 0; mt < 9; mt++)
        #pragma unroll
        for (int e = 0; e < 4; e++) acc[mt][e] = 0.f;

    #pragma unroll 1
    for (int kt = 0; kt < 4; kt++) {
        __syncthreads();
        // stage Wc slice: 144 rows x 64 k (bf16 hi/lo), 1152 uint4 each
        #pragma unroll
        for (int it = 0; it < 5; it++) {
            const int e = tid + 256 * it;
            if (e < 1152) {
                const int row = e >> 3, q = e & 7;
                *(uint4*)(smem + KF_AH + row * KSTR + q * 16) = g_WcH4[row * 32 + kt * 8 + q];
                *(uint4*)(smem + KF_AL + row * KSTR + q * 16) = g_WcL4[row * 32 + kt * 8 + q];
            }
        }
        // stage + split x slice: 64 ch x 64 m
        #pragma unroll
        for (int it = 0; it < 4; it++) {
            const int e = tid + 256 * it;            // < 1024
            const int c = e >> 4, f = e & 15;
            float4 v = *(const float4*)&x[((size_t)b * CH + kt * 64 + c) * HW + i0 * HWD + f * 4];
            uint32_t h0, l0, h1, l1;
            bsplit2(v.x, v.y, h0, l0);
            bsplit2(v.z, v.w, h1, l1);
            *(uint2*)(smem + KF_BH + c * KSTR + f * 8) = make_uint2(h0, h1);
            *(uint2*)(smem + KF_BL + c * KSTR + f * 8) = make_uint2(l0, l1);
        }
        __syncthreads();

        #pragma unroll
        for (int k16 = 0; k16 < 4; k16++) {
            uint32_t bh[2], bl[2];
            const uint32_t bbase = sb + (k16 * 16 + r) * KSTR + wid * 16;
            ldm_x2t(bh[0], bh[1], bbase + KF_BH);
            ldm_x2t(bl[0], bl[1], bbase + KF_BL);
            #pragma unroll
            for (int mt = 0; mt < 9; mt++) {
                uint32_t ah[4], al[4];
                const uint32_t abase = sb + (mt * 16 + r) * KSTR + k16 * 32 + hh * 16;
                ldm_x4(ah[0], ah[1], ah[2], ah[3], abase + KF_AH);
                ldm_x4(al[0], al[1], al[2], al[3], abase + KF_AL);
                mma_bf16(acc[mt], ah, bh);
                mma_bf16(acc[mt], ah, bl);
                mma_bf16(acc[mt], al, bh);
            }
        }
    }

    // ---- spill ker (+bias) to smem fp32 [144][68] ---------------------------
    __syncthreads();
    float* Ys = (float*)smem;
    {
        const int gq = lane >> 2;
        const int col = wid * 8 + (lane & 3) * 2;
        #pragma unroll
        for (int mt = 0; mt < 9; mt++) {
            const int row = mt * 16 + gq;
            const float b0 = sbc[row], b1 = sbc[row + 8];
            *(float2*)&Ys[row * 68 + col]       = make_float2(acc[mt][0] + b0, acc[mt][1] + b0);
            *(float2*)&Ys[(row + 8) * 68 + col] = make_float2(acc[mt][2] + b1, acc[mt][3] + b1);
        }
    }
    __syncthreads();

    // ---- fold over ki, split to bf16 hi/lo, write Kp in inv's A layout ------
    {
        const int g  = tid >> 4;            // 0..15
        const int ms = (tid & 15) * 4;      // m segment
        #pragma unroll
        for (int kj = 0; kj < 3; kj++) {
            const float* y1 = Ys + (g * 9 + 3 + kj) * 68;
            const float* y0 = Ys + (g * 9 + kj) * 68;
            const float* y2 = Ys + (g * 9 + 6 + kj) * 68;
            float v[4];
            #pragma unroll
            for (int mm = 0; mm < 4; mm++) {
                const int m = ms + mm;
                float t = y1[m];
                if (m < 63) t += y0[m + 1];
                if (m > 0)  t += y2[m - 1];
                v[mm] = t;
            }
            uint32_t h0, l0, h1, l1;
            bsplit2(v[0], v[1], h0, l0);
            bsplit2(v[2], v[3], h1, l1);
            const size_t row = (size_t)(b * G_ + g) * 192 + kj * 64 + i0;
            *(uint2*)((char*)g_KpH4 + row * 144 + ms * 2) = make_uint2(h0, h1);
            *(uint2*)((char*)g_KpL4 + row * 144 + ms * 2) = make_uint2(l0, l1);
        }
    }
}

// ---------------- kernel C: mma.sync main einsum (A pre-split) ---------------
#define A_STRB  144
#define OFF_AH  0
#define OFF_AL  27648      // 192*144
#define OFF_BH  55296
#define OFF_BL  64512
#define SMEM_MMA 73728
#define YSTR    68

__global__ __launch_bounds__(256, 2) void inv_mma(const float* __restrict__ x,
                                                  float* __restrict__ out) {
    extern __shared__ char smem[];
    const uint32_t sb = smem_u32(smem);
    const int c = blockIdx.x, g = blockIdx.y, b = blockIdx.z;
    const int tid  = threadIdx.x;
    const int wid  = tid >> 5, lane = tid & 31;
    const int wm   = wid & 3;          // M quadrant (48 rows)
    const int wn   = wid >> 2;         // N half (32 cols)

    // ---- copy pre-split A = Kp[b][g] (192 x 64 bf16 hi/lo, stride 144B) -----
    {
        const uint4* KH = g_KpH4 + (size_t)(b * G_ + g) * 192 * 9;
        const uint4* KL = g_KpL4 + (size_t)(b * G_ + g) * 192 * 9;
        #pragma unroll
        for (int it = 0; it < 7; it++) {
            const int e = tid + 256 * it;
            if (e < 1728) {
                *(uint4*)(smem + OFF_AH + e * 16) = KH[e];
                *(uint4*)(smem + OFF_AL + e * 16) = KL[e];
            }
        }
    }
    // ---- convert B = x[c] (64m x 64j) -> bf16 hi/lo --------------------------
    {
        const float* xc = x + ((size_t)(b * CH) + g * 16 + c) * HW;
        #pragma unroll
        for (int it = 0; it < 4; it++) {
            const int e4 = tid + 256 * it;             // < 1024
            const int row = e4 >> 4, q = (e4 & 15) << 2;
            float4 v = *(const float4*)&xc[row * 64 + q];
            uint32_t h0, l0, h1, l1;
            bsplit2(v.x, v.y, h0, l0);
            bsplit2(v.z, v.w, h1, l1);
            const uint32_t off = row * A_STRB + q * 2;
            *(uint2*)(smem + OFF_BH + off) = make_uint2(h0, h1);
            *(uint2*)(smem + OFF_BL + off) = make_uint2(l0, l1);
        }
    }
    __syncthreads();

    float acc[3][4][4];
    #pragma unroll
    for (int mt = 0; mt < 3; mt++)
        #pragma unroll
        for (int nt = 0; nt < 4; nt++)
            #pragma unroll
            for (int e = 0; e < 4; e++) acc[mt][nt][e] = 0.f;

    const int r  = lane & 15;
    const int hh = lane >> 4;
    #pragma unroll
    for (int k = 0; k < 4; k++) {
        uint32_t ah[3][4], al[3][4], bh[4][2], bl[4][2];
        #pragma unroll
        for (int mt = 0; mt < 3; mt++) {
            const uint32_t base = sb + (wm * 48 + mt * 16 + r) * A_STRB + k * 32 + hh * 16;
            ldm_x4(ah[mt][0], ah[mt][1], ah[mt][2], ah[mt][3], base + OFF_AH);
            ldm_x4(al[mt][0], al[mt][1], al[mt][2], al[mt][3], base + OFF_AL);
        }
        #pragma unroll
        for (int nt = 0; nt < 4; nt++) {
            const uint32_t base = sb + (k * 16 + r) * A_STRB + (wn * 32 + nt * 8) * 2;
            ldm_x2t(bh[nt][0], bh[nt][1], base + OFF_BH);
            ldm_x2t(bl[nt][0], bl[nt][1], base + OFF_BL);
        }
        #pragma unroll
        for (int mt = 0; mt < 3; mt++)
            #pragma unroll
            for (int nt = 0; nt < 4; nt++) {
                mma_bf16(acc[mt][nt], ah[mt], bh[nt]);
                mma_bf16(acc[mt][nt], ah[mt], bl[nt]);
                mma_bf16(acc[mt][nt], al[mt], bh[nt]);
            }
    }

    // ---- spill Y (192 x 64 fp32) to smem -------------------------------------
    __syncthreads();
    float* Ys = (float*)smem;
    const int gq = lane >> 2, cb = (lane & 3) * 2;
    #pragma unroll
    for (int mt = 0; mt < 3; mt++)
        #pragma unroll
        for (int nt = 0; nt < 4; nt++) {
            const int row = wm * 48 + mt * 16 + gq;
            const int col = wn * 32 + nt * 8 + cb;
            *(float2*)&Ys[row * YSTR + col]       = make_float2(acc[mt][nt][0], acc[mt][nt][1]);
            *(float2*)&Ys[(row + 8) * YSTR + col] = make_float2(acc[mt][nt][2], acc[mt][nt][3]);
        }
    __syncthreads();

    // ---- combine shifted rows, coalesced float4 stores -----------------------
    const int i  = tid >> 2;
    const int jb = (tid & 3) * 16;
    float* op = out + (((size_t)b * CH + g * 16 + c) * HWD + i) * HWD;
    const float* y0 = Ys + i * YSTR;
    const float* y1 = Ys + (64 + i) * YSTR;
    const float* y2 = Ys + (128 + i) * YSTR;
    #pragma unroll
    for (int u = 0; u < 4; u++) {
        const int j0 = jb + u * 4;
        float vals[4];
        #pragma unroll
        for (int e = 0; e < 4; e++) {
            const int j = j0 + e;
            float v = y1[j];
            if (j > 0)  v += y0[j - 1];
            if (j < 63) v += y2[j + 1];
            vals[e] = v;
        }
        *(float4*)&op[j0] = make_float4(vals[0], vals[1], vals[2], vals[3]);
    }
}

// ---------------- launch ------------------------------------------------------
extern "C" void kernel_launch(void* const* d_in, const int* in_sizes, int n_in,
                              void* d_out, int out_size) {
    const float* x        = (const float*)d_in[0];
    const float* W_reduce = (const float*)d_in[1];
    const float* b_reduce = (const float*)d_in[2];
    const float* W_span   = (const float*)d_in[3];
    const float* b_span   = (const float*)d_in[4];
    float* out = (float*)d_out;

    cudaFuncSetAttribute(ker_fold, cudaFuncAttributeMaxDynamicSharedMemorySize, KF_SMEM);
    cudaFuncSetAttribute(inv_mma,  cudaFuncAttributeMaxDynamicSharedMemorySize, SMEM_MMA);

    fuse_weights<<<RROWS, 128>>>(W_reduce, b_reduce, W_span, b_span);
    ker_fold<<<dim3(HWD, B_), 256, KF_SMEM>>>(x);
    inv_mma<<<dim3(16, G_, B_), 256, SMEM_MMA>>>(x, out);
}

// round 7
// speedup vs baseline: 3.2999x; 1.0365x over previous
#include <cuda_runtime.h>
#include <cuda_bf16.h>
#include <cstdint>

// Problem constants
#define CH      256
#define G_      16
#define RROWS   144
#define RED_CH  128
#define B_      8
#define HWD     64
#define HW      4096

// ---------------- mma.sync helpers (sm_80+, plain sm_103 OK) ----------------
__device__ __forceinline__ uint32_t smem_u32(const void* p) {
    uint32_t a;
    asm("{ .reg .u64 t; cvta.to.shared.u64 t, %1; cvt.u32.u64 %0, t; }" : "=r"(a) : "l"(p));
    return a;
}
__device__ __forceinline__ void ldm_x4(uint32_t& r0, uint32_t& r1, uint32_t& r2,
                                       uint32_t& r3, uint32_t addr) {
    asm volatile("ldmatrix.sync.aligned.m8n8.x4.shared.b16 {%0,%1,%2,%3}, [%4];"
        : "=r"(r0), "=r"(r1), "=r"(r2), "=r"(r3) : "r"(addr));
}
__device__ __forceinline__ void ldm_x2t(uint32_t& r0, uint32_t& r1, uint32_t addr) {
    asm volatile("ldmatrix.sync.aligned.m8n8.x2.trans.shared.b16 {%0,%1}, [%2];"
        : "=r"(r0), "=r"(r1) : "r"(addr));
}
__device__ __forceinline__ void mma_bf16(float* c, const uint32_t* a, const uint32_t* b) {
    asm volatile("mma.sync.aligned.m16n8k16.row.col.f32.bf16.bf16.f32 "
        "{%0,%1,%2,%3}, {%4,%5,%6,%7}, {%8,%9}, {%0,%1,%2,%3};"
        : "+f"(c[0]), "+f"(c[1]), "+f"(c[2]), "+f"(c[3])
        : "r"(a[0]), "r"(a[1]), "r"(a[2]), "r"(a[3]), "r"(b[0]), "r"(b[1]));
}
__device__ __forceinline__ void bsplit2(float a, float b, uint32_t& hi, uint32_t& lo) {
    __nv_bfloat162 h = __floats2bfloat162_rn(a, b);
    hi = *reinterpret_cast<uint32_t*>(&h);
    float ra = a - __bfloat162float(h.x);
    float rb = b - __bfloat162float(h.y);
    __nv_bfloat162 l = __floats2bfloat162_rn(ra, rb);
    lo = *reinterpret_cast<uint32_t*>(&l);
}

// ---------------- device scratch (pre-split bf16) ----------------------------
__device__ uint4 g_WcH4[RROWS * 32];          // 144 x 256 bf16 (32 uint4/row)
__device__ uint4 g_WcL4[RROWS * 32];
__device__ uint4 g_KpH4[B_ * G_ * 192 * 9];   // per (b,g): 192 rows x 144B
__device__ uint4 g_KpL4[B_ * G_ * 192 * 9];
__device__ float g_bc[RROWS];

// ---------------- kernel A: fuse weights, parallel-k reduction --------------
__global__ __launch_bounds__(256) void fuse_weights(
        const float* __restrict__ W_reduce, const float* __restrict__ b_reduce,
        const float* __restrict__ W_span,   const float* __restrict__ b_span) {
    __shared__ float ws[RED_CH];
    __shared__ float ps[256 * 2];
    const int r   = blockIdx.x;           // 0..143
    const int tid = threadIdx.x;          // 256
    if (tid < RED_CH) ws[tid] = W_span[r * RED_CH + tid];
    __syncthreads();

    const int c2 = tid & 127;             // column pair
    const int oh = tid >> 7;              // o half
    const float2* Wr2 = (const float2*)W_reduce;   // [o][128]
    float s0 = 0.f, s1 = 0.f;
    const int o0 = oh * 64;
    #pragma unroll 8
    for (int o = o0; o < o0 + 64; o++) {
        const float2 w = Wr2[o * 128 + c2];
        const float a = ws[o];
        s0 += a * w.x;
        s1 += a * w.y;
    }
    ps[tid * 2]     = s0;
    ps[tid * 2 + 1] = s1;
    __syncthreads();

    if (tid < 128) {
        s0 = ps[tid * 2]     + ps[(tid + 128) * 2];
        s1 = ps[tid * 2 + 1] + ps[(tid + 128) * 2 + 1];
        uint32_t hi, lo;
        bsplit2(s0, s1, hi, lo);
        ((uint32_t*)g_WcH4)[r * 128 + tid] = hi;
        ((uint32_t*)g_WcL4)[r * 128 + tid] = lo;
    }
    if (tid < 32) {
        float s = 0.f;
        #pragma unroll
        for (int o = tid; o < RED_CH; o += 32) s += ws[o] * b_reduce[o];
        #pragma unroll
        for (int d = 16; d > 0; d >>= 1) s += __shfl_xor_sync(0xffffffffu, s, d);
        if (tid == 0) g_bc[r] = s + b_span[r];
    }
}

// ---------------- kernel B: ker GEMM + fold, tensorized ----------------------
// CTA = (image row i0, b). D[144 r][64 m] = Wc @ x[b][:, i0, :], K=256 (4 tiles).
// Epilogue: fold over ki (shift along m) + bias, write pre-split bf16 Kp.
#define KSTR   144          // smem row stride (bytes): 64 bf16 + 16 pad
#define KF_AH  0
#define KF_AL  20736        // 144*144
#define KF_BH  41472
#define KF_BL  50688        // +64*144
#define KF_BC  59904
#define KF_SMEM (KF_BC + 576)

__global__ __launch_bounds__(256, 2) void ker_fold(const float* __restrict__ x) {
    extern __shared__ char smem[];
    const uint32_t sb = smem_u32(smem);
    float* sbc = (float*)(smem + KF_BC);
    const int i0 = blockIdx.x;          // 0..63
    const int b  = blockIdx.y;
    const int tid = threadIdx.x;
    const int wid = tid >> 5, lane = tid & 31;
    const int r  = lane & 15, hh = lane >> 4;

    if (tid < RROWS) sbc[tid] = g_bc[tid];

    float acc[9][4];
    #pragma unroll
    for (int mt = 0; mt < 9; mt++)
        #pragma unroll
        for (int e = 0; e < 4; e++) acc[mt][e] = 0.f;

    #pragma unroll 1
    for (int kt = 0; kt < 4; kt++) {
        __syncthreads();
        // stage Wc slice: 144 rows x 64 k (bf16 hi/lo), 1152 uint4 each
        #pragma unroll
        for (int it = 0; it < 5; it++) {
            const int e = tid + 256 * it;
            if (e < 1152) {
                const int row = e >> 3, q = e & 7;
                *(uint4*)(smem + KF_AH + row * KSTR + q * 16) = g_WcH4[row * 32 + kt * 8 + q];
                *(uint4*)(smem + KF_AL + row * KSTR + q * 16) = g_WcL4[row * 32 + kt * 8 + q];
            }
        }
        // stage + split x slice: 64 ch x 64 m
        #pragma unroll
        for (int it = 0; it < 4; it++) {
            const int e = tid + 256 * it;            // < 1024
            const int c = e >> 4, f = e & 15;
            float4 v = *(const float4*)&x[((size_t)b * CH + kt * 64 + c) * HW + i0 * HWD + f * 4];
            uint32_t h0, l0, h1, l1;
            bsplit2(v.x, v.y, h0, l0);
            bsplit2(v.z, v.w, h1, l1);
            *(uint2*)(smem + KF_BH + c * KSTR + f * 8) = make_uint2(h0, h1);
            *(uint2*)(smem + KF_BL + c * KSTR + f * 8) = make_uint2(l0, l1);
        }
        __syncthreads();

        #pragma unroll
        for (int k16 = 0; k16 < 4; k16++) {
            uint32_t bh[2], bl[2];
            const uint32_t bbase = sb + (k16 * 16 + r) * KSTR + wid * 16;
            ldm_x2t(bh[0], bh[1], bbase + KF_BH);
            ldm_x2t(bl[0], bl[1], bbase + KF_BL);
            #pragma unroll
            for (int mt = 0; mt < 9; mt++) {
                uint32_t ah[4], al[4];
                const uint32_t abase = sb + (mt * 16 + r) * KSTR + k16 * 32 + hh * 16;
                ldm_x4(ah[0], ah[1], ah[2], ah[3], abase + KF_AH);
                ldm_x4(al[0], al[1], al[2], al[3], abase + KF_AL);
                mma_bf16(acc[mt], ah, bh);
                mma_bf16(acc[mt], ah, bl);
                mma_bf16(acc[mt], al, bh);
            }
        }
    }

    // ---- spill ker (+bias) to smem fp32 [144][68] ---------------------------
    __syncthreads();
    float* Ys = (float*)smem;
    {
        const int gq = lane >> 2;
        const int col = wid * 8 + (lane & 3) * 2;
        #pragma unroll
        for (int mt = 0; mt < 9; mt++) {
            const int row = mt * 16 + gq;
            const float b0 = sbc[row], b1 = sbc[row + 8];
            *(float2*)&Ys[row * 68 + col]       = make_float2(acc[mt][0] + b0, acc[mt][1] + b0);
            *(float2*)&Ys[(row + 8) * 68 + col] = make_float2(acc[mt][2] + b1, acc[mt][3] + b1);
        }
    }
    __syncthreads();

    // ---- fold over ki, split to bf16 hi/lo, write Kp in inv's A layout ------
    {
        const int g  = tid >> 4;            // 0..15
        const int ms = (tid & 15) * 4;      // m segment
        #pragma unroll
        for (int kj = 0; kj < 3; kj++) {
            const float* y1 = Ys + (g * 9 + 3 + kj) * 68;
            const float* y0 = Ys + (g * 9 + kj) * 68;
            const float* y2 = Ys + (g * 9 + 6 + kj) * 68;
            float v[4];
            #pragma unroll
            for (int mm = 0; mm < 4; mm++) {
                const int m = ms + mm;
                float t = y1[m];
                if (m < 63) t += y0[m + 1];
                if (m > 0)  t += y2[m - 1];
                v[mm] = t;
            }
            uint32_t h0, l0, h1, l1;
            bsplit2(v[0], v[1], h0, l0);
            bsplit2(v[2], v[3], h1, l1);
            const size_t row = (size_t)(b * G_ + g) * 192 + kj * 64 + i0;
            *(uint2*)((char*)g_KpH4 + row * 144 + ms * 2) = make_uint2(h0, h1);
            *(uint2*)((char*)g_KpL4 + row * 144 + ms * 2) = make_uint2(l0, l1);
        }
    }
}

// ---------------- kernel C: mma.sync main einsum (A pre-split) ---------------
#define A_STRB  144
#define OFF_AH  0
#define OFF_AL  27648      // 192*144
#define OFF_BH  55296
#define OFF_BL  64512
#define SMEM_MMA 73728
#define YSTR    68

__global__ __launch_bounds__(256, 2) void inv_mma(const float* __restrict__ x,
                                                  float* __restrict__ out) {
    extern __shared__ char smem[];
    const uint32_t sb = smem_u32(smem);
    const int c = blockIdx.x, g = blockIdx.y, b = blockIdx.z;
    const int tid  = threadIdx.x;
    const int wid  = tid >> 5, lane = tid & 31;
    const int wm   = wid & 3;          // M quadrant (48 rows)
    const int wn   = wid >> 2;         // N half (32 cols)

    // ---- copy pre-split A = Kp[b][g] (192 x 64 bf16 hi/lo, stride 144B) -----
    {
        const uint4* KH = g_KpH4 + (size_t)(b * G_ + g) * 192 * 9;
        const uint4* KL = g_KpL4 + (size_t)(b * G_ + g) * 192 * 9;
        #pragma unroll
        for (int it = 0; it < 7; it++) {
            const int e = tid + 256 * it;
            if (e < 1728) {
                *(uint4*)(smem + OFF_AH + e * 16) = KH[e];
                *(uint4*)(smem + OFF_AL + e * 16) = KL[e];
            }
        }
    }
    // ---- convert B = x[c] (64m x 64j) -> bf16 hi/lo --------------------------
    {
        const float* xc = x + ((size_t)(b * CH) + g * 16 + c) * HW;
        #pragma unroll
        for (int it = 0; it < 4; it++) {
            const int e4 = tid + 256 * it;             // < 1024
            const int row = e4 >> 4, q = (e4 & 15) << 2;
            float4 v = *(const float4*)&xc[row * 64 + q];
            uint32_t h0, l0, h1, l1;
            bsplit2(v.x, v.y, h0, l0);
            bsplit2(v.z, v.w, h1, l1);
            const uint32_t off = row * A_STRB + q * 2;
            *(uint2*)(smem + OFF_BH + off) = make_uint2(h0, h1);
            *(uint2*)(smem + OFF_BL + off) = make_uint2(l0, l1);
        }
    }
    __syncthreads();

    float acc[3][4][4];
    #pragma unroll
    for (int mt = 0; mt < 3; mt++)
        #pragma unroll
        for (int nt = 0; nt < 4; nt++)
            #pragma unroll
            for (int e = 0; e < 4; e++) acc[mt][nt][e] = 0.f;

    const int r  = lane & 15;
    const int hh = lane >> 4;
    #pragma unroll
    for (int k = 0; k < 4; k++) {
        uint32_t ah[3][4], al[3][4], bh[4][2], bl[4][2];
        #pragma unroll
        for (int mt = 0; mt < 3; mt++) {
            const uint32_t base = sb + (wm * 48 + mt * 16 + r) * A_STRB + k * 32 + hh * 16;
            ldm_x4(ah[mt][0], ah[mt][1], ah[mt][2], ah[mt][3], base + OFF_AH);
            ldm_x4(al[mt][0], al[mt][1], al[mt][2], al[mt][3], base + OFF_AL);
        }
        #pragma unroll
        for (int nt = 0; nt < 4; nt++) {
            const uint32_t base = sb + (k * 16 + r) * A_STRB + (wn * 32 + nt * 8) * 2;
            ldm_x2t(bh[nt][0], bh[nt][1], base + OFF_BH);
            ldm_x2t(bl[nt][0], bl[nt][1], base + OFF_BL);
        }
        #pragma unroll
        for (int mt = 0; mt < 3; mt++)
            #pragma unroll
            for (int nt = 0; nt < 4; nt++) {
                mma_bf16(acc[mt][nt], ah[mt], bh[nt]);
                mma_bf16(acc[mt][nt], ah[mt], bl[nt]);
                mma_bf16(acc[mt][nt], al[mt], bh[nt]);
            }
    }

    // ---- spill Y (192 x 64 fp32) to smem -------------------------------------
    __syncthreads();
    float* Ys = (float*)smem;
    const int gq = lane >> 2, cb = (lane & 3) * 2;
    #pragma unroll
    for (int mt = 0; mt < 3; mt++)
        #pragma unroll
        for (int nt = 0; nt < 4; nt++) {
            const int row = wm * 48 + mt * 16 + gq;
            const int col = wn * 32 + nt * 8 + cb;
            *(float2*)&Ys[row * YSTR + col]       = make_float2(acc[mt][nt][0], acc[mt][nt][1]);
            *(float2*)&Ys[(row + 8) * YSTR + col] = make_float2(acc[mt][nt][2], acc[mt][nt][3]);
        }
    __syncthreads();

    // ---- combine shifted rows, coalesced float4 stores -----------------------
    const int i  = tid >> 2;
    const int jb = (tid & 3) * 16;
    float* op = out + (((size_t)b * CH + g * 16 + c) * HWD + i) * HWD;
    const float* y0 = Ys + i * YSTR;
    const float* y1 = Ys + (64 + i) * YSTR;
    const float* y2 = Ys + (128 + i) * YSTR;
    #pragma unroll
    for (int u = 0; u < 4; u++) {
        const int j0 = jb + u * 4;
        float vals[4];
        #pragma unroll
        for (int e = 0; e < 4; e++) {
            const int j = j0 + e;
            float v = y1[j];
            if (j > 0)  v += y0[j - 1];
            if (j < 63) v += y2[j + 1];
            vals[e] = v;
        }
        *(float4*)&op[j0] = make_float4(vals[0], vals[1], vals[2], vals[3]);
    }
}

// ---------------- launch ------------------------------------------------------
extern "C" void kernel_launch(void* const* d_in, const int* in_sizes, int n_in,
                              void* d_out, int out_size) {
    const float* x        = (const float*)d_in[0];
    const float* W_reduce = (const float*)d_in[1];
    const float* b_reduce = (const float*)d_in[2];
    const float* W_span   = (const float*)d_in[3];
    const float* b_span   = (const float*)d_in[4];
    float* out = (float*)d_out;

    cudaFuncSetAttribute(ker_fold, cudaFuncAttributeMaxDynamicSharedMemorySize, KF_SMEM);
    cudaFuncSetAttribute(inv_mma,  cudaFuncAttributeMaxDynamicSharedMemorySize, SMEM_MMA);

    fuse_weights<<<RROWS, 256>>>(W_reduce, b_reduce, W_span, b_span);
    ker_fold<<<dim3(HWD, B_), 256, KF_SMEM>>>(x);
    inv_mma<<<dim3(16, G_, B_), 256, SMEM_MMA>>>(x, out);
}

// round 8
// speedup vs baseline: 3.6199x; 1.0970x over previous
#include <cuda_runtime.h>
#include <cuda_bf16.h>
#include <cstdint>

// Problem constants
#define CH      256
#define G_      16
#define RROWS   144
#define RED_CH  128
#define B_      8
#define HWD     64
#define HW      4096

// ---------------- mma.sync helpers ------------------------------------------
__device__ __forceinline__ uint32_t smem_u32(const void* p) {
    uint32_t a;
    asm("{ .reg .u64 t; cvta.to.shared.u64 t, %1; cvt.u32.u64 %0, t; }" : "=r"(a) : "l"(p));
    return a;
}
__device__ __forceinline__ void ldm_x4(uint32_t& r0, uint32_t& r1, uint32_t& r2,
                                       uint32_t& r3, uint32_t addr) {
    asm volatile("ldmatrix.sync.aligned.m8n8.x4.shared.b16 {%0,%1,%2,%3}, [%4];"
        : "=r"(r0), "=r"(r1), "=r"(r2), "=r"(r3) : "r"(addr));
}
__device__ __forceinline__ void ldm_x2t(uint32_t& r0, uint32_t& r1, uint32_t addr) {
    asm volatile("ldmatrix.sync.aligned.m8n8.x2.trans.shared.b16 {%0,%1}, [%2];"
        : "=r"(r0), "=r"(r1) : "r"(addr));
}
__device__ __forceinline__ void mma_bf16(float* c, const uint32_t* a, const uint32_t* b) {
    asm volatile("mma.sync.aligned.m16n8k16.row.col.f32.bf16.bf16.f32 "
        "{%0,%1,%2,%3}, {%4,%5,%6,%7}, {%8,%9}, {%0,%1,%2,%3};"
        : "+f"(c[0]), "+f"(c[1]), "+f"(c[2]), "+f"(c[3])
        : "r"(a[0]), "r"(a[1]), "r"(a[2]), "r"(a[3]), "r"(b[0]), "r"(b[1]));
}
__device__ __forceinline__ void bsplit2(float a, float b, uint32_t& hi, uint32_t& lo) {
    __nv_bfloat162 h = __floats2bfloat162_rn(a, b);
    hi = *reinterpret_cast<uint32_t*>(&h);
    float ra = a - __bfloat162float(h.x);
    float rb = b - __bfloat162float(h.y);
    __nv_bfloat162 l = __floats2bfloat162_rn(ra, rb);
    lo = *reinterpret_cast<uint32_t*>(&l);
}

// ---------------- device scratch (pre-split bf16) ----------------------------
__device__ uint4 g_WcH4[RROWS * 32];          // 144 x 256 bf16
__device__ uint4 g_WcL4[RROWS * 32];
// A' = Kp transposed: per (b,g) 64 rows(i) x 192 cols(kj,m), 384 B/row tight
__device__ uint4 g_KpH4[B_ * G_ * 64 * 24];
__device__ uint4 g_KpL4[B_ * G_ * 64 * 24];
__device__ float g_bc[RROWS];

// ---------------- kernel A: fuse weights, 4-way k-split ---------------------
__global__ __launch_bounds__(512) void fuse_weights(
        const float* __restrict__ W_reduce, const float* __restrict__ b_reduce,
        const float* __restrict__ W_span,   const float* __restrict__ b_span) {
    __shared__ float ws[RED_CH];
    __shared__ float2 ps[512];
    const int r   = blockIdx.x;           // 0..143
    const int tid = threadIdx.x;          // 512
    if (tid < RED_CH) ws[tid] = W_span[r * RED_CH + tid];
    __syncthreads();

    const int c2 = tid & 127;
    const int o0 = (tid >> 7) * 32;
    const float2* Wr2 = (const float2*)W_reduce;   // [o][128]
    float s0 = 0.f, s1 = 0.f;
    #pragma unroll 8
    for (int o = o0; o < o0 + 32; o++) {
        const float2 w = Wr2[o * 128 + c2];
        const float a = ws[o];
        s0 += a * w.x;
        s1 += a * w.y;
    }
    ps[tid] = make_float2(s0, s1);
    __syncthreads();

    if (tid < 128) {
        float2 p0 = ps[tid], p1 = ps[tid + 128], p2 = ps[tid + 256], p3 = ps[tid + 384];
        s0 = (p0.x + p1.x) + (p2.x + p3.x);
        s1 = (p0.y + p1.y) + (p2.y + p3.y);
        uint32_t hi, lo;
        bsplit2(s0, s1, hi, lo);
        ((uint32_t*)g_WcH4)[r * 128 + tid] = hi;
        ((uint32_t*)g_WcL4)[r * 128 + tid] = lo;
    }
    if (tid < 32) {
        float s = 0.f;
        #pragma unroll
        for (int o = tid; o < RED_CH; o += 32) s += ws[o] * b_reduce[o];
        #pragma unroll
        for (int d = 16; d > 0; d >>= 1) s += __shfl_xor_sync(0xffffffffu, s, d);
        if (tid == 0) g_bc[r] = s + b_span[r];
    }
}

// ---------------- kernel B: ker GEMM + fold (epilogue -> transposed A') -----
#define KSTR   144
#define KF_AH  0
#define KF_AL  20736
#define KF_BH  41472
#define KF_BL  50688
#define KF_BC  59904
#define KF_SMEM (KF_BC + 576)

__global__ __launch_bounds__(256, 2) void ker_fold(const float* __restrict__ x) {
    extern __shared__ char smem[];
    const uint32_t sb = smem_u32(smem);
    float* sbc = (float*)(smem + KF_BC);
    const int i0 = blockIdx.x;
    const int b  = blockIdx.y;
    const int tid = threadIdx.x;
    const int wid = tid >> 5, lane = tid & 31;
    const int r  = lane & 15, hh = lane >> 4;

    if (tid < RROWS) sbc[tid] = g_bc[tid];

    float acc[9][4];
    #pragma unroll
    for (int mt = 0; mt < 9; mt++)
        #pragma unroll
        for (int e = 0; e < 4; e++) acc[mt][e] = 0.f;

    #pragma unroll 1
    for (int kt = 0; kt < 4; kt++) {
        __syncthreads();
        #pragma unroll
        for (int it = 0; it < 5; it++) {
            const int e = tid + 256 * it;
            if (e < 1152) {
                const int row = e >> 3, q = e & 7;
                *(uint4*)(smem + KF_AH + row * KSTR + q * 16) = g_WcH4[row * 32 + kt * 8 + q];
                *(uint4*)(smem + KF_AL + row * KSTR + q * 16) = g_WcL4[row * 32 + kt * 8 + q];
            }
        }
        #pragma unroll
        for (int it = 0; it < 4; it++) {
            const int e = tid + 256 * it;
            const int c = e >> 4, f = e & 15;
            float4 v = *(const float4*)&x[((size_t)b * CH + kt * 64 + c) * HW + i0 * HWD + f * 4];
            uint32_t h0, l0, h1, l1;
            bsplit2(v.x, v.y, h0, l0);
            bsplit2(v.z, v.w, h1, l1);
            *(uint2*)(smem + KF_BH + c * KSTR + f * 8) = make_uint2(h0, h1);
            *(uint2*)(smem + KF_BL + c * KSTR + f * 8) = make_uint2(l0, l1);
        }
        __syncthreads();

        #pragma unroll
        for (int k16 = 0; k16 < 4; k16++) {
            uint32_t bh[2], bl[2];
            const uint32_t bbase = sb + (k16 * 16 + r) * KSTR + wid * 16;
            ldm_x2t(bh[0], bh[1], bbase + KF_BH);
            ldm_x2t(bl[0], bl[1], bbase + KF_BL);
            #pragma unroll
            for (int mt = 0; mt < 9; mt++) {
                uint32_t ah[4], al[4];
                const uint32_t abase = sb + (mt * 16 + r) * KSTR + k16 * 32 + hh * 16;
                ldm_x4(ah[0], ah[1], ah[2], ah[3], abase + KF_AH);
                ldm_x4(al[0], al[1], al[2], al[3], abase + KF_AL);
                mma_bf16(acc[mt], ah, bh);
                mma_bf16(acc[mt], ah, bl);
                mma_bf16(acc[mt], al, bh);
            }
        }
    }

    // ---- spill ker (+bias) to smem fp32 [144][68] ---------------------------
    __syncthreads();
    float* Ys = (float*)smem;
    {
        const int gq = lane >> 2;
        const int col = wid * 8 + (lane & 3) * 2;
        #pragma unroll
        for (int mt = 0; mt < 9; mt++) {
            const int row = mt * 16 + gq;
            const float b0 = sbc[row], b1 = sbc[row + 8];
            *(float2*)&Ys[row * 68 + col]       = make_float2(acc[mt][0] + b0, acc[mt][1] + b0);
            *(float2*)&Ys[(row + 8) * 68 + col] = make_float2(acc[mt][2] + b1, acc[mt][3] + b1);
        }
    }
    __syncthreads();

    // ---- fold over ki, write A' transposed: row i0, cols (kj*64+m) ---------
    {
        const int g  = tid >> 4;
        const int ms = (tid & 15) * 4;
        const size_t arow = ((size_t)(b * G_ + g) * 64 + i0) * 384;   // bytes
        #pragma unroll
        for (int kj = 0; kj < 3; kj++) {
            const float* y1 = Ys + (g * 9 + 3 + kj) * 68;
            const float* y0 = Ys + (g * 9 + kj) * 68;
            const float* y2 = Ys + (g * 9 + 6 + kj) * 68;
            float v[4];
            #pragma unroll
            for (int mm = 0; mm < 4; mm++) {
                const int m = ms + mm;
                float t = y1[m];
                if (m < 63) t += y0[m + 1];
                if (m > 0)  t += y2[m - 1];
                v[mm] = t;
            }
            uint32_t h0, l0, h1, l1;
            bsplit2(v[0], v[1], h0, l0);
            bsplit2(v[2], v[3], h1, l1);
            const uint32_t cb = (kj * 64 + ms) * 2;
            *(uint2*)((char*)g_KpH4 + arow + cb) = make_uint2(h0, h1);
            *(uint2*)((char*)g_KpL4 + arow + cb) = make_uint2(l0, l1);
        }
    }
}

// ---------------- kernel C: shifted-B single GEMM ----------------------------
// CTA = (c, g, b). out[64 i][64 j] = A'[i][(kj,m)] @ B'[(kj,m)][j],
// B'[(kj,m)][j] = x[c][m][j+kj-1] (halo zeros). Direct STG epilogue.
#define IA_STR  400            // smem A' row stride (384 data + 16 pad)
#define I_AH    0
#define I_AL    25600          // 64*400
#define I_BH    51200
#define I_BL    78848          // +192*144
#define SMEM_INV 106496        // +192*144

__global__ __launch_bounds__(256, 2) void inv_mma(const float* __restrict__ x,
                                                  float* __restrict__ out) {
    extern __shared__ char smem[];
    const uint32_t sb = smem_u32(smem);
    const int c = blockIdx.x, g = blockIdx.y, b = blockIdx.z;
    const int tid  = threadIdx.x;
    const int wid  = tid >> 5, lane = tid & 31;
    const int wm   = wid & 3;          // i quadrant (16 rows)
    const int wn   = wid >> 2;         // j half (32 cols)

    // ---- phase 1: stage x[c] fp32 into scratch (A region, 64 x 68) ----------
    float* scr = (float*)smem;
    {
        const float* xc = x + ((size_t)(b * CH) + g * 16 + c) * HW;
        #pragma unroll
        for (int it = 0; it < 4; it++) {
            const int e4 = tid + 256 * it;             // < 1024
            const int m = e4 >> 4, j4 = (e4 & 15) << 2;
            *(float4*)&scr[m * 68 + j4] = *(const float4*)&xc[m * 64 + j4];
        }
    }
    __syncthreads();

    // ---- phase 2: build B' (3 shifted bf16 hi/lo copies) ---------------------
    #pragma unroll
    for (int it = 0; it < 4; it++) {
        const int e = tid + 256 * it;                  // < 1024
        const int m = e >> 4, j0 = (e & 15) << 2;
        const float* sr = scr + m * 68;
        const float am1 = (j0 > 0) ? sr[j0 - 1] : 0.f;
        const float a0 = sr[j0], a1 = sr[j0 + 1], a2 = sr[j0 + 2], a3 = sr[j0 + 3];
        const float a4 = (j0 < 60) ? sr[j0 + 4] : 0.f;
        uint32_t h[5], l[5];
        bsplit2(am1, a0, h[0], l[0]);
        bsplit2(a0,  a1, h[1], l[1]);
        bsplit2(a1,  a2, h[2], l[2]);
        bsplit2(a2,  a3, h[3], l[3]);
        bsplit2(a3,  a4, h[4], l[4]);
        const uint32_t cbyte = j0 * 2;
        // kj = 0: x[j-1]  -> row m
        *(uint2*)(smem + I_BH + m * 144 + cbyte) = make_uint2(h[0], h[2]);
        *(uint2*)(smem + I_BL + m * 144 + cbyte) = make_uint2(l[0], l[2]);
        // kj = 1: x[j]    -> row 64 + m
        *(uint2*)(smem + I_BH + (64 + m) * 144 + cbyte) = make_uint2(h[1], h[3]);
        *(uint2*)(smem + I_BL + (64 + m) * 144 + cbyte) = make_uint2(l[1], l[3]);
        // kj = 2: x[j+1]  -> row 128 + m
        *(uint2*)(smem + I_BH + (128 + m) * 144 + cbyte) = make_uint2(h[2], h[4]);
        *(uint2*)(smem + I_BL + (128 + m) * 144 + cbyte) = make_uint2(l[2], l[4]);
    }
    __syncthreads();

    // ---- phase 3: copy pre-split A' (overwrites scratch) ---------------------
    {
        const uint4* KH = g_KpH4 + (size_t)(b * G_ + g) * 1536;
        const uint4* KL = g_KpL4 + (size_t)(b * G_ + g) * 1536;
        #pragma unroll
        for (int it = 0; it < 6; it++) {
            const int e = tid + 256 * it;              // < 1536
            const int row = e / 24, q = e - row * 24;
            *(uint4*)(smem + I_AH + row * IA_STR + q * 16) = KH[e];
            *(uint4*)(smem + I_AL + row * IA_STR + q * 16) = KL[e];
        }
    }
    __syncthreads();

    // ---- phase 4: K=192 mma, acc = out tile directly --------------------------
    float acc[4][4];
    #pragma unroll
    for (int nt = 0; nt < 4; nt++)
        #pragma unroll
        for (int e = 0; e < 4; e++) acc[nt][e] = 0.f;

    const int r  = lane & 15;
    const int hh = lane >> 4;
    #pragma unroll
    for (int k = 0; k < 12; k++) {
        uint32_t ah[4], al[4];
        const uint32_t abase = sb + I_AH + (wm * 16 + r) * IA_STR + k * 32 + hh * 16;
        ldm_x4(ah[0], ah[1], ah[2], ah[3], abase);
        ldm_x4(al[0], al[1], al[2], al[3], abase + (I_AL - I_AH));
        uint32_t bh[4][2], bl[4][2];
        #pragma unroll
        for (int nt = 0; nt < 4; nt++) {
            const uint32_t bbase = sb + I_BH + (k * 16 + r) * 144 + (wn * 32 + nt * 8) * 2;
            ldm_x2t(bh[nt][0], bh[nt][1], bbase);
            ldm_x2t(bl[nt][0], bl[nt][1], bbase + (I_BL - I_BH));
        }
        #pragma unroll
        for (int nt = 0; nt < 4; nt++) {
            mma_bf16(acc[nt], ah, bh[nt]);
            mma_bf16(acc[nt], ah, bl[nt]);
            mma_bf16(acc[nt], al, bh[nt]);
        }
    }

    // ---- phase 5: direct store ------------------------------------------------
    {
        const int gq = lane >> 2, cb = (lane & 3) * 2;
        const int i0 = wm * 16 + gq;
        float* op = out + ((size_t)(b * CH) + g * 16 + c) * HW;
        #pragma unroll
        for (int nt = 0; nt < 4; nt++) {
            const int j = wn * 32 + nt * 8 + cb;
            *(float2*)&op[i0 * 64 + j]       = make_float2(acc[nt][0], acc[nt][1]);
            *(float2*)&op[(i0 + 8) * 64 + j] = make_float2(acc[nt][2], acc[nt][3]);
        }
    }
}

// ---------------- launch ------------------------------------------------------
extern "C" void kernel_launch(void* const* d_in, const int* in_sizes, int n_in,
                              void* d_out, int out_size) {
    const float* x        = (const float*)d_in[0];
    const float* W_reduce = (const float*)d_in[1];
    const float* b_reduce = (const float*)d_in[2];
    const float* W_span   = (const float*)d_in[3];
    const float* b_span   = (const float*)d_in[4];
    float* out = (float*)d_out;

    cudaFuncSetAttribute(ker_fold, cudaFuncAttributeMaxDynamicSharedMemorySize, KF_SMEM);
    cudaFuncSetAttribute(inv_mma,  cudaFuncAttributeMaxDynamicSharedMemorySize, SMEM_INV);

    fuse_weights<<<RROWS, 512>>>(W_reduce, b_reduce, W_span, b_span);
    ker_fold<<<dim3(HWD, B_), 256, KF_SMEM>>>(x);
    inv_mma<<<dim3(16, G_, B_), 256, SMEM_INV>>>(x, out);
}

// round 9
// speedup vs baseline: 3.7880x; 1.0464x over previous
#include <cuda_runtime.h>
#include <cuda_bf16.h>
#include <cstdint>

// Problem constants
#define CH      256
#define G_      16
#define RROWS   144
#define RED_CH  128
#define B_      8
#define HWD     64
#define HW      4096

// ---------------- mma.sync / async helpers -----------------------------------
__device__ __forceinline__ uint32_t smem_u32(const void* p) {
    uint32_t a;
    asm("{ .reg .u64 t; cvta.to.shared.u64 t, %1; cvt.u32.u64 %0, t; }" : "=r"(a) : "l"(p));
    return a;
}
__device__ __forceinline__ void ldm_x4(uint32_t& r0, uint32_t& r1, uint32_t& r2,
                                       uint32_t& r3, uint32_t addr) {
    asm volatile("ldmatrix.sync.aligned.m8n8.x4.shared.b16 {%0,%1,%2,%3}, [%4];"
        : "=r"(r0), "=r"(r1), "=r"(r2), "=r"(r3) : "r"(addr));
}
__device__ __forceinline__ void ldm_x2t(uint32_t& r0, uint32_t& r1, uint32_t addr) {
    asm volatile("ldmatrix.sync.aligned.m8n8.x2.trans.shared.b16 {%0,%1}, [%2];"
        : "=r"(r0), "=r"(r1) : "r"(addr));
}
__device__ __forceinline__ void mma_bf16(float* c, const uint32_t* a, const uint32_t* b) {
    asm volatile("mma.sync.aligned.m16n8k16.row.col.f32.bf16.bf16.f32 "
        "{%0,%1,%2,%3}, {%4,%5,%6,%7}, {%8,%9}, {%0,%1,%2,%3};"
        : "+f"(c[0]), "+f"(c[1]), "+f"(c[2]), "+f"(c[3])
        : "r"(a[0]), "r"(a[1]), "r"(a[2]), "r"(a[3]), "r"(b[0]), "r"(b[1]));
}
__device__ __forceinline__ void bsplit2(float a, float b, uint32_t& hi, uint32_t& lo) {
    __nv_bfloat162 h = __floats2bfloat162_rn(a, b);
    hi = *reinterpret_cast<uint32_t*>(&h);
    float ra = a - __bfloat162float(h.x);
    float rb = b - __bfloat162float(h.y);
    __nv_bfloat162 l = __floats2bfloat162_rn(ra, rb);
    lo = *reinterpret_cast<uint32_t*>(&l);
}
__device__ __forceinline__ void cp16(uint32_t sdst, const void* gsrc) {
    asm volatile("cp.async.cg.shared.global [%0], [%1], 16;" :: "r"(sdst), "l"(gsrc));
}
#define CP_COMMIT() asm volatile("cp.async.commit_group;" ::: "memory")
#define CP_WAIT0()  asm volatile("cp.async.wait_group 0;" ::: "memory")

// ---------------- device scratch (pre-split bf16) ----------------------------
__device__ uint4 g_WcH4[RROWS * 32];          // 144 x 256 bf16
__device__ uint4 g_WcL4[RROWS * 32];
// A' = Kp transposed: per (b,g) 64 rows(i) x 192 cols(kj,m), 384 B/row tight
__device__ uint4 g_KpH4[B_ * G_ * 64 * 24];
__device__ uint4 g_KpL4[B_ * G_ * 64 * 24];
__device__ float g_bc[RROWS];

// ---------------- kernel A: fuse weights, 8-way k-split ---------------------
__global__ __launch_bounds__(1024) void fuse_weights(
        const float* __restrict__ W_reduce, const float* __restrict__ b_reduce,
        const float* __restrict__ W_span,   const float* __restrict__ b_span) {
    __shared__ float ws[RED_CH];
    __shared__ float2 ps[1024];
    const int r   = blockIdx.x;           // 0..143
    const int tid = threadIdx.x;          // 1024
    if (tid < RED_CH) ws[tid] = W_span[r * RED_CH + tid];
    __syncthreads();

    const int c2 = tid & 127;
    const int o0 = (tid >> 7) * 16;
    const float2* Wr2 = (const float2*)W_reduce;   // [o][128]
    float s0 = 0.f, s1 = 0.f;
    #pragma unroll
    for (int o = o0; o < o0 + 16; o++) {
        const float2 w = Wr2[o * 128 + c2];
        const float a = ws[o];
        s0 += a * w.x;
        s1 += a * w.y;
    }
    ps[tid] = make_float2(s0, s1);
    __syncthreads();

    if (tid < 128) {
        #pragma unroll
        for (int p = 1; p < 8; p++) {
            float2 t = ps[tid + p * 128];
            s0 = ps[tid].x;  // keep accumulation explicit
            s1 = ps[tid].y;
            (void)s0; (void)s1;
        }
        s0 = 0.f; s1 = 0.f;
        #pragma unroll
        for (int p = 0; p < 8; p++) {
            float2 t = ps[tid + p * 128];
            s0 += t.x; s1 += t.y;
        }
        uint32_t hi, lo;
        bsplit2(s0, s1, hi, lo);
        ((uint32_t*)g_WcH4)[r * 128 + tid] = hi;
        ((uint32_t*)g_WcL4)[r * 128 + tid] = lo;
    }
    if (tid < 32) {
        float s = 0.f;
        #pragma unroll
        for (int o = tid; o < RED_CH; o += 32) s += ws[o] * b_reduce[o];
        #pragma unroll
        for (int d = 16; d > 0; d >>= 1) s += __shfl_xor_sync(0xffffffffu, s, d);
        if (tid == 0) g_bc[r] = s + b_span[r];
    }
}

// ---------------- kernel B: ker GEMM + fold (async staging) -----------------
#define KSTR   144
#define KF_AH  0
#define KF_AL  20736
#define KF_BH  41472
#define KF_BL  50688
#define KF_BC  59904
#define KF_SMEM (KF_BC + 576)

__global__ __launch_bounds__(256, 2) void ker_fold(const float* __restrict__ x) {
    extern __shared__ char smem[];
    const uint32_t sb = smem_u32(smem);
    float* sbc = (float*)(smem + KF_BC);
    const int i0 = blockIdx.x;
    const int b  = blockIdx.y;
    const int tid = threadIdx.x;
    const int wid = tid >> 5, lane = tid & 31;
    const int r  = lane & 15, hh = lane >> 4;

    if (tid < RROWS) sbc[tid] = g_bc[tid];

    float acc[9][4];
    #pragma unroll
    for (int mt = 0; mt < 9; mt++)
        #pragma unroll
        for (int e = 0; e < 4; e++) acc[mt][e] = 0.f;

    // prefetch kt=0 x slice into regs
    float4 breg[4];
    #pragma unroll
    for (int it = 0; it < 4; it++) {
        const int e = tid + 256 * it;
        const int c = e >> 4, f = e & 15;
        breg[it] = *(const float4*)&x[((size_t)b * CH + c) * HW + i0 * HWD + f * 4];
    }

    #pragma unroll 1
    for (int kt = 0; kt < 4; kt++) {
        __syncthreads();                 // smem free (prev MMA done)
        // async stage Wc slice (pre-split, no reg round-trip)
        #pragma unroll
        for (int it = 0; it < 5; it++) {
            const int e = tid + 256 * it;
            if (e < 1152) {
                const int row = e >> 3, q = e & 7;
                cp16(sb + KF_AH + row * KSTR + q * 16, &g_WcH4[row * 32 + kt * 8 + q]);
                cp16(sb + KF_AL + row * KSTR + q * 16, &g_WcL4[row * 32 + kt * 8 + q]);
            }
        }
        CP_COMMIT();
        // convert prefetched x regs -> smem B
        #pragma unroll
        for (int it = 0; it < 4; it++) {
            const int e = tid + 256 * it;
            const int c = e >> 4, f = e & 15;
            const float4 v = breg[it];
            uint32_t h0, l0, h1, l1;
            bsplit2(v.x, v.y, h0, l0);
            bsplit2(v.z, v.w, h1, l1);
            *(uint2*)(smem + KF_BH + c * KSTR + f * 8) = make_uint2(h0, h1);
            *(uint2*)(smem + KF_BL + c * KSTR + f * 8) = make_uint2(l0, l1);
        }
        // prefetch next kt x slice (latency hidden under wait+MMA)
        if (kt < 3) {
            #pragma unroll
            for (int it = 0; it < 4; it++) {
                const int e = tid + 256 * it;
                const int c = e >> 4, f = e & 15;
                breg[it] = *(const float4*)&x[((size_t)b * CH + (kt + 1) * 64 + c) * HW + i0 * HWD + f * 4];
            }
        }
        CP_WAIT0();
        __syncthreads();

        #pragma unroll
        for (int k16 = 0; k16 < 4; k16++) {
            uint32_t bh[2], bl[2];
            const uint32_t bbase = sb + (k16 * 16 + r) * KSTR + wid * 16;
            ldm_x2t(bh[0], bh[1], bbase + KF_BH);
            ldm_x2t(bl[0], bl[1], bbase + KF_BL);
            #pragma unroll
            for (int mt = 0; mt < 9; mt++) {
                uint32_t ah[4], al[4];
                const uint32_t abase = sb + (mt * 16 + r) * KSTR + k16 * 32 + hh * 16;
                ldm_x4(ah[0], ah[1], ah[2], ah[3], abase + KF_AH);
                ldm_x4(al[0], al[1], al[2], al[3], abase + KF_AL);
                mma_bf16(acc[mt], ah, bh);
                mma_bf16(acc[mt], ah, bl);
                mma_bf16(acc[mt], al, bh);
            }
        }
    }

    // ---- spill ker (+bias) to smem fp32 [144][68] ---------------------------
    __syncthreads();
    float* Ys = (float*)smem;
    {
        const int gq = lane >> 2;
        const int col = wid * 8 + (lane & 3) * 2;
        #pragma unroll
        for (int mt = 0; mt < 9; mt++) {
            const int row = mt * 16 + gq;
            const float b0 = sbc[row], b1 = sbc[row + 8];
            *(float2*)&Ys[row * 68 + col]       = make_float2(acc[mt][0] + b0, acc[mt][1] + b0);
            *(float2*)&Ys[(row + 8) * 68 + col] = make_float2(acc[mt][2] + b1, acc[mt][3] + b1);
        }
    }
    __syncthreads();

    // ---- fold over ki, write A' transposed: row i0, cols (kj*64+m) ---------
    {
        const int g  = tid >> 4;
        const int ms = (tid & 15) * 4;
        const size_t arow = ((size_t)(b * G_ + g) * 64 + i0) * 384;   // bytes
        #pragma unroll
        for (int kj = 0; kj < 3; kj++) {
            const float* y1 = Ys + (g * 9 + 3 + kj) * 68;
            const float* y0 = Ys + (g * 9 + kj) * 68;
            const float* y2 = Ys + (g * 9 + 6 + kj) * 68;
            float v[4];
            #pragma unroll
            for (int mm = 0; mm < 4; mm++) {
                const int m = ms + mm;
                float t = y1[m];
                if (m < 63) t += y0[m + 1];
                if (m > 0)  t += y2[m - 1];
                v[mm] = t;
            }
            uint32_t h0, l0, h1, l1;
            bsplit2(v[0], v[1], h0, l0);
            bsplit2(v[2], v[3], h1, l1);
            const uint32_t cb = (kj * 64 + ms) * 2;
            *(uint2*)((char*)g_KpH4 + arow + cb) = make_uint2(h0, h1);
            *(uint2*)((char*)g_KpL4 + arow + cb) = make_uint2(l0, l1);
        }
    }
}

// ---------------- kernel C: shifted-B single GEMM, async A' ------------------
#define IA_STR  400
#define I_AH    0
#define I_AL    25600
#define I_BH    51200
#define I_BL    78848
#define SMEM_INV 106496

__global__ __launch_bounds__(256, 2) void inv_mma(const float* __restrict__ x,
                                                  float* __restrict__ out) {
    extern __shared__ char smem[];
    const uint32_t sb = smem_u32(smem);
    const int c = blockIdx.x, g = blockIdx.y, b = blockIdx.z;
    const int tid  = threadIdx.x;
    const int wid  = tid >> 5, lane = tid & 31;
    const int wm   = wid & 3;          // i quadrant (16 rows)
    const int wn   = wid >> 2;         // j half (32 cols)

    // ---- kick off async A' copy (pre-split, L1-bypass) -----------------------
    {
        const uint4* KH = g_KpH4 + (size_t)(b * G_ + g) * 1536;
        const uint4* KL = g_KpL4 + (size_t)(b * G_ + g) * 1536;
        #pragma unroll
        for (int it = 0; it < 6; it++) {
            const int e = tid + 256 * it;              // < 1536
            const int row = e / 24, q = e - row * 24;
            cp16(sb + I_AH + row * IA_STR + q * 16, KH + e);
            cp16(sb + I_AL + row * IA_STR + q * 16, KL + e);
        }
        CP_COMMIT();
    }

    // ---- build B' (3 shifted bf16 hi/lo copies) directly from global --------
    {
        const float* xc = x + ((size_t)(b * CH) + g * 16 + c) * HW;
        #pragma unroll
        for (int it = 0; it < 4; it++) {
            const int e = tid + 256 * it;                  // < 1024
            const int m = e >> 4, j0 = (e & 15) << 2;
            const float* row = xc + m * 64;
            const float4 v = *(const float4*)&row[j0];
            const float am1 = (j0 > 0)  ? row[j0 - 1] : 0.f;
            const float a4  = (j0 < 60) ? row[j0 + 4] : 0.f;
            uint32_t h[5], l[5];
            bsplit2(am1, v.x, h[0], l[0]);
            bsplit2(v.x, v.y, h[1], l[1]);
            bsplit2(v.y, v.z, h[2], l[2]);
            bsplit2(v.z, v.w, h[3], l[3]);
            bsplit2(v.w, a4,  h[4], l[4]);
            const uint32_t cbyte = j0 * 2;
            // kj = 0: x[j-1]  -> row m
            *(uint2*)(smem + I_BH + m * 144 + cbyte) = make_uint2(h[0], h[2]);
            *(uint2*)(smem + I_BL + m * 144 + cbyte) = make_uint2(l[0], l[2]);
            // kj = 1: x[j]    -> row 64 + m
            *(uint2*)(smem + I_BH + (64 + m) * 144 + cbyte) = make_uint2(h[1], h[3]);
            *(uint2*)(smem + I_BL + (64 + m) * 144 + cbyte) = make_uint2(l[1], l[3]);
            // kj = 2: x[j+1]  -> row 128 + m
            *(uint2*)(smem + I_BH + (128 + m) * 144 + cbyte) = make_uint2(h[2], h[4]);
            *(uint2*)(smem + I_BL + (128 + m) * 144 + cbyte) = make_uint2(l[2], l[4]);
        }
    }
    CP_WAIT0();
    __syncthreads();

    // ---- K=192 mma, acc = out tile directly ----------------------------------
    float acc[4][4];
    #pragma unroll
    for (int nt = 0; nt < 4; nt++)
        #pragma unroll
        for (int e = 0; e < 4; e++) acc[nt][e] = 0.f;

    const int r  = lane & 15;
    const int hh = lane >> 4;
    #pragma unroll
    for (int k = 0; k < 12; k++) {
        uint32_t ah[4], al[4];
        const uint32_t abase = sb + I_AH + (wm * 16 + r) * IA_STR + k * 32 + hh * 16;
        ldm_x4(ah[0], ah[1], ah[2], ah[3], abase);
        ldm_x4(al[0], al[1], al[2], al[3], abase + (I_AL - I_AH));
        uint32_t bh[4][2], bl[4][2];
        #pragma unroll
        for (int nt = 0; nt < 4; nt++) {
            const uint32_t bbase = sb + I_BH + (k * 16 + r) * 144 + (wn * 32 + nt * 8) * 2;
            ldm_x2t(bh[nt][0], bh[nt][1], bbase);
            ldm_x2t(bl[nt][0], bl[nt][1], bbase + (I_BL - I_BH));
        }
        #pragma unroll
        for (int nt = 0; nt < 4; nt++) {
            mma_bf16(acc[nt], ah, bh[nt]);
            mma_bf16(acc[nt], ah, bl[nt]);
            mma_bf16(acc[nt], al, bh[nt]);
        }
    }

    // ---- direct store ---------------------------------------------------------
    {
        const int gq = lane >> 2, cb = (lane & 3) * 2;
        const int i0 = wm * 16 + gq;
        float* op = out + ((size_t)(b * CH) + g * 16 + c) * HW;
        #pragma unroll
        for (int nt = 0; nt < 4; nt++) {
            const int j = wn * 32 + nt * 8 + cb;
            *(float2*)&op[i0 * 64 + j]       = make_float2(acc[nt][0], acc[nt][1]);
            *(float2*)&op[(i0 + 8) * 64 + j] = make_float2(acc[nt][2], acc[nt][3]);
        }
    }
}

// ---------------- launch ------------------------------------------------------
extern "C" void kernel_launch(void* const* d_in, const int* in_sizes, int n_in,
                              void* d_out, int out_size) {
    const float* x        = (const float*)d_in[0];
    const float* W_reduce = (const float*)d_in[1];
    const float* b_reduce = (const float*)d_in[2];
    const float* W_span   = (const float*)d_in[3];
    const float* b_span   = (const float*)d_in[4];
    float* out = (float*)d_out;

    cudaFuncSetAttribute(ker_fold, cudaFuncAttributeMaxDynamicSharedMemorySize, KF_SMEM);
    cudaFuncSetAttribute(inv_mma,  cudaFuncAttributeMaxDynamicSharedMemorySize, SMEM_INV);

    fuse_weights<<<RROWS, 1024>>>(W_reduce, b_reduce, W_span, b_span);
    ker_fold<<<dim3(HWD, B_), 256, KF_SMEM>>>(x);
    inv_mma<<<dim3(16, G_, B_), 256, SMEM_INV>>>(x, out);
}

// round 10
// speedup vs baseline: 3.8561x; 1.0180x over previous
#include <cuda_runtime.h>
#include <cuda_bf16.h>
#include <cstdint>

// Problem constants
#define CH      256
#define G_      16
#define RROWS   144
#define RED_CH  128
#define B_      8
#define HWD     64
#define HW      4096

// ---------------- mma.sync / async helpers -----------------------------------
__device__ __forceinline__ uint32_t smem_u32(const void* p) {
    uint32_t a;
    asm("{ .reg .u64 t; cvta.to.shared.u64 t, %1; cvt.u32.u64 %0, t; }" : "=r"(a) : "l"(p));
    return a;
}
__device__ __forceinline__ void ldm_x4(uint32_t& r0, uint32_t& r1, uint32_t& r2,
                                       uint32_t& r3, uint32_t addr) {
    asm volatile("ldmatrix.sync.aligned.m8n8.x4.shared.b16 {%0,%1,%2,%3}, [%4];"
        : "=r"(r0), "=r"(r1), "=r"(r2), "=r"(r3) : "r"(addr));
}
__device__ __forceinline__ void ldm_x2t(uint32_t& r0, uint32_t& r1, uint32_t addr) {
    asm volatile("ldmatrix.sync.aligned.m8n8.x2.trans.shared.b16 {%0,%1}, [%2];"
        : "=r"(r0), "=r"(r1) : "r"(addr));
}
__device__ __forceinline__ void mma_bf16(float* c, const uint32_t* a, const uint32_t* b) {
    asm volatile("mma.sync.aligned.m16n8k16.row.col.f32.bf16.bf16.f32 "
        "{%0,%1,%2,%3}, {%4,%5,%6,%7}, {%8,%9}, {%0,%1,%2,%3};"
        : "+f"(c[0]), "+f"(c[1]), "+f"(c[2]), "+f"(c[3])
        : "r"(a[0]), "r"(a[1]), "r"(a[2]), "r"(a[3]), "r"(b[0]), "r"(b[1]));
}
__device__ __forceinline__ void bsplit2(float a, float b, uint32_t& hi, uint32_t& lo) {
    __nv_bfloat162 h = __floats2bfloat162_rn(a, b);
    hi = *reinterpret_cast<uint32_t*>(&h);
    float ra = a - __bfloat162float(h.x);
    float rb = b - __bfloat162float(h.y);
    __nv_bfloat162 l = __floats2bfloat162_rn(ra, rb);
    lo = *reinterpret_cast<uint32_t*>(&l);
}
__device__ __forceinline__ void cp16(uint32_t sdst, const void* gsrc) {
    asm volatile("cp.async.cg.shared.global [%0], [%1], 16;" :: "r"(sdst), "l"(gsrc));
}
#define CP_COMMIT() asm volatile("cp.async.commit_group;" ::: "memory")
#define CP_WAIT0()  asm volatile("cp.async.wait_group 0;" ::: "memory")

// ---------------- device scratch (pre-split bf16) ----------------------------
__device__ uint4 g_WcH4[RROWS * 32];          // 144 x 256 bf16
__device__ uint4 g_WcL4[RROWS * 32];
// A' = Kp transposed: per (b,g) 64 rows(i) x 192 cols(kj,m), 384 B/row tight
__device__ uint4 g_KpH4[B_ * G_ * 64 * 24];
__device__ uint4 g_KpL4[B_ * G_ * 64 * 24];
__device__ float g_bc[RROWS];

// ---------------- kernel A: fuse weights, 8-way k-split ---------------------
__global__ __launch_bounds__(1024) void fuse_weights(
        const float* __restrict__ W_reduce, const float* __restrict__ b_reduce,
        const float* __restrict__ W_span,   const float* __restrict__ b_span) {
    __shared__ float ws[RED_CH];
    __shared__ float2 ps[1024];
    const int r   = blockIdx.x;           // 0..143
    const int tid = threadIdx.x;          // 1024
    if (tid < RED_CH) ws[tid] = W_span[r * RED_CH + tid];
    __syncthreads();

    const int c2 = tid & 127;
    const int o0 = (tid >> 7) * 16;
    const float2* Wr2 = (const float2*)W_reduce;   // [o][128]
    float s0 = 0.f, s1 = 0.f;
    #pragma unroll
    for (int o = o0; o < o0 + 16; o++) {
        const float2 w = Wr2[o * 128 + c2];
        const float a = ws[o];
        s0 += a * w.x;
        s1 += a * w.y;
    }
    ps[tid] = make_float2(s0, s1);
    __syncthreads();

    if (tid < 128) {
        s0 = 0.f; s1 = 0.f;
        #pragma unroll
        for (int p = 0; p < 8; p++) {
            float2 t = ps[tid + p * 128];
            s0 += t.x; s1 += t.y;
        }
        uint32_t hi, lo;
        bsplit2(s0, s1, hi, lo);
        ((uint32_t*)g_WcH4)[r * 128 + tid] = hi;
        ((uint32_t*)g_WcL4)[r * 128 + tid] = lo;
    }
    if (tid < 32) {
        float s = 0.f;
        #pragma unroll
        for (int o = tid; o < RED_CH; o += 32) s += ws[o] * b_reduce[o];
        #pragma unroll
        for (int d = 16; d > 0; d >>= 1) s += __shfl_xor_sync(0xffffffffu, s, d);
        if (tid == 0) g_bc[r] = s + b_span[r];
    }
}

// ---------------- kernel B: ker GEMM + fold (async staging) -----------------
#define KSTR   144
#define KF_AH  0
#define KF_AL  20736
#define KF_BH  41472
#define KF_BL  50688
#define KF_BC  59904
#define KF_SMEM (KF_BC + 576)

__global__ __launch_bounds__(256, 2) void ker_fold(const float* __restrict__ x) {
    extern __shared__ char smem[];
    const uint32_t sb = smem_u32(smem);
    float* sbc = (float*)(smem + KF_BC);
    const int i0 = blockIdx.x;
    const int b  = blockIdx.y;
    const int tid = threadIdx.x;
    const int wid = tid >> 5, lane = tid & 31;
    const int r  = lane & 15, hh = lane >> 4;

    if (tid < RROWS) sbc[tid] = g_bc[tid];

    float acc[9][4];
    #pragma unroll
    for (int mt = 0; mt < 9; mt++)
        #pragma unroll
        for (int e = 0; e < 4; e++) acc[mt][e] = 0.f;

    // prefetch kt=0 x slice into regs
    float4 breg[4];
    #pragma unroll
    for (int it = 0; it < 4; it++) {
        const int e = tid + 256 * it;
        const int c = e >> 4, f = e & 15;
        breg[it] = *(const float4*)&x[((size_t)b * CH + c) * HW + i0 * HWD + f * 4];
    }

    #pragma unroll 1
    for (int kt = 0; kt < 4; kt++) {
        __syncthreads();                 // smem free (prev MMA done)
        #pragma unroll
        for (int it = 0; it < 5; it++) {
            const int e = tid + 256 * it;
            if (e < 1152) {
                const int row = e >> 3, q = e & 7;
                cp16(sb + KF_AH + row * KSTR + q * 16, &g_WcH4[row * 32 + kt * 8 + q]);
                cp16(sb + KF_AL + row * KSTR + q * 16, &g_WcL4[row * 32 + kt * 8 + q]);
            }
        }
        CP_COMMIT();
        #pragma unroll
        for (int it = 0; it < 4; it++) {
            const int e = tid + 256 * it;
            const int c = e >> 4, f = e & 15;
            const float4 v = breg[it];
            uint32_t h0, l0, h1, l1;
            bsplit2(v.x, v.y, h0, l0);
            bsplit2(v.z, v.w, h1, l1);
            *(uint2*)(smem + KF_BH + c * KSTR + f * 8) = make_uint2(h0, h1);
            *(uint2*)(smem + KF_BL + c * KSTR + f * 8) = make_uint2(l0, l1);
        }
        if (kt < 3) {
            #pragma unroll
            for (int it = 0; it < 4; it++) {
                const int e = tid + 256 * it;
                const int c = e >> 4, f = e & 15;
                breg[it] = *(const float4*)&x[((size_t)b * CH + (kt + 1) * 64 + c) * HW + i0 * HWD + f * 4];
            }
        }
        CP_WAIT0();
        __syncthreads();

        #pragma unroll
        for (int k16 = 0; k16 < 4; k16++) {
            uint32_t bh[2], bl[2];
            const uint32_t bbase = sb + (k16 * 16 + r) * KSTR + wid * 16;
            ldm_x2t(bh[0], bh[1], bbase + KF_BH);
            ldm_x2t(bl[0], bl[1], bbase + KF_BL);
            #pragma unroll
            for (int mt = 0; mt < 9; mt++) {
                uint32_t ah[4], al[4];
                const uint32_t abase = sb + (mt * 16 + r) * KSTR + k16 * 32 + hh * 16;
                ldm_x4(ah[0], ah[1], ah[2], ah[3], abase + KF_AH);
                ldm_x4(al[0], al[1], al[2], al[3], abase + KF_AL);
                mma_bf16(acc[mt], ah, bh);
                mma_bf16(acc[mt], ah, bl);
                mma_bf16(acc[mt], al, bh);
            }
        }
    }

    // ---- spill ker (+bias) to smem fp32 [144][68] ---------------------------
    __syncthreads();
    float* Ys = (float*)smem;
    {
        const int gq = lane >> 2;
        const int col = wid * 8 + (lane & 3) * 2;
        #pragma unroll
        for (int mt = 0; mt < 9; mt++) {
            const int row = mt * 16 + gq;
            const float b0 = sbc[row], b1 = sbc[row + 8];
            *(float2*)&Ys[row * 68 + col]       = make_float2(acc[mt][0] + b0, acc[mt][1] + b0);
            *(float2*)&Ys[(row + 8) * 68 + col] = make_float2(acc[mt][2] + b1, acc[mt][3] + b1);
        }
    }
    __syncthreads();

    // ---- fold over ki, write A' transposed: row i0, cols (kj*64+m) ---------
    {
        const int g  = tid >> 4;
        const int ms = (tid & 15) * 4;
        const size_t arow = ((size_t)(b * G_ + g) * 64 + i0) * 384;   // bytes
        #pragma unroll
        for (int kj = 0; kj < 3; kj++) {
            const float* y1 = Ys + (g * 9 + 3 + kj) * 68;
            const float* y0 = Ys + (g * 9 + kj) * 68;
            const float* y2 = Ys + (g * 9 + 6 + kj) * 68;
            float v[4];
            #pragma unroll
            for (int mm = 0; mm < 4; mm++) {
                const int m = ms + mm;
                float t = y1[m];
                if (m < 63) t += y0[m + 1];
                if (m > 0)  t += y2[m - 1];
                v[mm] = t;
            }
            uint32_t h0, l0, h1, l1;
            bsplit2(v[0], v[1], h0, l0);
            bsplit2(v[2], v[3], h1, l1);
            const uint32_t cb = (kj * 64 + ms) * 2;
            *(uint2*)((char*)g_KpH4 + arow + cb) = make_uint2(h0, h1);
            *(uint2*)((char*)g_KpL4 + arow + cb) = make_uint2(l0, l1);
        }
    }
}

// ---------------- kernel C: shifted-B GEMM, 4 channels per CTA ---------------
// CTA = (cq, g, b). A' resident; loop cc in 0..3 over channels.
#define IA_STR  400
#define I_AH    0
#define I_AL    25600
#define I_BH    51200
#define I_BL    78848
#define SMEM_INV 106496

__global__ __launch_bounds__(256, 2) void inv_mma(const float* __restrict__ x,
                                                  float* __restrict__ out) {
    extern __shared__ char smem[];
    const uint32_t sb = smem_u32(smem);
    const int cq = blockIdx.x, g = blockIdx.y, b = blockIdx.z;
    const int tid  = threadIdx.x;
    const int wid  = tid >> 5, lane = tid & 31;
    const int wm   = wid & 3;          // i quadrant (16 rows)
    const int wn   = wid >> 2;         // j half (32 cols)
    const int ch0  = g * 16 + cq * 4;
    const float* xbase = x + ((size_t)(b * CH) + ch0) * HW;

    // ---- async A' copy once (pre-split, resident for all 4 channels) --------
    {
        const uint4* KH = g_KpH4 + (size_t)(b * G_ + g) * 1536;
        const uint4* KL = g_KpL4 + (size_t)(b * G_ + g) * 1536;
        #pragma unroll
        for (int it = 0; it < 6; it++) {
            const int e = tid + 256 * it;              // < 1536
            const int row = e / 24, q = e - row * 24;
            cp16(sb + I_AH + row * IA_STR + q * 16, KH + e);
            cp16(sb + I_AL + row * IA_STR + q * 16, KL + e);
        }
        CP_COMMIT();
    }

    // per-thread x chunk coordinates (4 chunks of 4 floats + 2 halo scalars)
    int mArr[4], j0Arr[4];
    #pragma unroll
    for (int it = 0; it < 4; it++) {
        const int e = tid + 256 * it;
        mArr[it] = e >> 4;
        j0Arr[it] = (e & 15) << 2;
    }

    // prefetch x(channel 0)
    float4 v[4]; float am1[4], a4[4];
    #pragma unroll
    for (int it = 0; it < 4; it++) {
        const float* row = xbase + mArr[it] * 64;
        v[it]  = *(const float4*)&row[j0Arr[it]];
        am1[it] = (j0Arr[it] > 0)  ? row[j0Arr[it] - 1] : 0.f;
        a4[it]  = (j0Arr[it] < 60) ? row[j0Arr[it] + 4] : 0.f;
    }

    const int r  = lane & 15;
    const int hh = lane >> 4;
    const int gq = lane >> 2, cb = (lane & 3) * 2;
    const int i0 = wm * 16 + gq;

    #pragma unroll 1
    for (int cc = 0; cc < 4; cc++) {
        if (cc > 0) __syncthreads();        // prev MMA done reading B'
        // ---- build B'(cc) from prefetched regs ------------------------------
        #pragma unroll
        for (int it = 0; it < 4; it++) {
            const int m = mArr[it], j0 = j0Arr[it];
            uint32_t h[5], l[5];
            bsplit2(am1[it], v[it].x, h[0], l[0]);
            bsplit2(v[it].x, v[it].y, h[1], l[1]);
            bsplit2(v[it].y, v[it].z, h[2], l[2]);
            bsplit2(v[it].z, v[it].w, h[3], l[3]);
            bsplit2(v[it].w, a4[it],  h[4], l[4]);
            const uint32_t cbyte = j0 * 2;
            *(uint2*)(smem + I_BH + m * 144 + cbyte) = make_uint2(h[0], h[2]);
            *(uint2*)(smem + I_BL + m * 144 + cbyte) = make_uint2(l[0], l[2]);
            *(uint2*)(smem + I_BH + (64 + m) * 144 + cbyte) = make_uint2(h[1], h[3]);
            *(uint2*)(smem + I_BL + (64 + m) * 144 + cbyte) = make_uint2(l[1], l[3]);
            *(uint2*)(smem + I_BH + (128 + m) * 144 + cbyte) = make_uint2(h[2], h[4]);
            *(uint2*)(smem + I_BL + (128 + m) * 144 + cbyte) = make_uint2(l[2], l[4]);
        }
        if (cc == 0) CP_WAIT0();            // A' resident from here on
        __syncthreads();

        // ---- prefetch x(cc+1) (hidden under MMA) -----------------------------
        if (cc < 3) {
            const float* xn = xbase + (cc + 1) * HW;
            #pragma unroll
            for (int it = 0; it < 4; it++) {
                const float* row = xn + mArr[it] * 64;
                v[it]  = *(const float4*)&row[j0Arr[it]];
                am1[it] = (j0Arr[it] > 0)  ? row[j0Arr[it] - 1] : 0.f;
                a4[it]  = (j0Arr[it] < 60) ? row[j0Arr[it] + 4] : 0.f;
            }
        }

        // ---- K=192 mma, acc = out tile --------------------------------------
        float acc[4][4];
        #pragma unroll
        for (int nt = 0; nt < 4; nt++)
            #pragma unroll
            for (int e = 0; e < 4; e++) acc[nt][e] = 0.f;

        #pragma unroll
        for (int k = 0; k < 12; k++) {
            uint32_t ah[4], al[4];
            const uint32_t abase = sb + I_AH + (wm * 16 + r) * IA_STR + k * 32 + hh * 16;
            ldm_x4(ah[0], ah[1], ah[2], ah[3], abase);
            ldm_x4(al[0], al[1], al[2], al[3], abase + (I_AL - I_AH));
            uint32_t bh[4][2], bl[4][2];
            #pragma unroll
            for (int nt = 0; nt < 4; nt++) {
                const uint32_t bbase = sb + I_BH + (k * 16 + r) * 144 + (wn * 32 + nt * 8) * 2;
                ldm_x2t(bh[nt][0], bh[nt][1], bbase);
                ldm_x2t(bl[nt][0], bl[nt][1], bbase + (I_BL - I_BH));
            }
            #pragma unroll
            for (int nt = 0; nt < 4; nt++) {
                mma_bf16(acc[nt], ah, bh[nt]);
                mma_bf16(acc[nt], ah, bl[nt]);
                mma_bf16(acc[nt], al, bh[nt]);
            }
        }

        // ---- direct store -----------------------------------------------------
        float* op = out + ((size_t)(b * CH) + ch0 + cc) * HW;
        #pragma unroll
        for (int nt = 0; nt < 4; nt++) {
            const int j = wn * 32 + nt * 8 + cb;
            *(float2*)&op[i0 * 64 + j]       = make_float2(acc[nt][0], acc[nt][1]);
            *(float2*)&op[(i0 + 8) * 64 + j] = make_float2(acc[nt][2], acc[nt][3]);
        }
    }
}

// ---------------- launch ------------------------------------------------------
extern "C" void kernel_launch(void* const* d_in, const int* in_sizes, int n_in,
                              void* d_out, int out_size) {
    const float* x        = (const float*)d_in[0];
    const float* W_reduce = (const float*)d_in[1];
    const float* b_reduce = (const float*)d_in[2];
    const float* W_span   = (const float*)d_in[3];
    const float* b_span   = (const float*)d_in[4];
    float* out = (float*)d_out;

    cudaFuncSetAttribute(ker_fold, cudaFuncAttributeMaxDynamicSharedMemorySize, KF_SMEM);
    cudaFuncSetAttribute(inv_mma,  cudaFuncAttributeMaxDynamicSharedMemorySize, SMEM_INV);

    fuse_weights<<<RROWS, 1024>>>(W_reduce, b_reduce, W_span, b_span);
    ker_fold<<<dim3(HWD, B_), 256, KF_SMEM>>>(x);
    inv_mma<<<dim3(4, G_, B_), 256, SMEM_INV>>>(x, out);
}

// round 11
// speedup vs baseline: 4.1852x; 1.0853x over previous
#include <cuda_runtime.h>
#include <cuda_bf16.h>
#include <cstdint>

// Problem constants
#define CH      256
#define G_      16
#define RROWS   144
#define RED_CH  128
#define B_      8
#define HWD     64
#define HW      4096

// ---------------- mma.sync / async helpers -----------------------------------
__device__ __forceinline__ uint32_t smem_u32(const void* p) {
    uint32_t a;
    asm("{ .reg .u64 t; cvta.to.shared.u64 t, %1; cvt.u32.u64 %0, t; }" : "=r"(a) : "l"(p));
    return a;
}
__device__ __forceinline__ void ldm_x4(uint32_t& r0, uint32_t& r1, uint32_t& r2,
                                       uint32_t& r3, uint32_t addr) {
    asm volatile("ldmatrix.sync.aligned.m8n8.x4.shared.b16 {%0,%1,%2,%3}, [%4];"
        : "=r"(r0), "=r"(r1), "=r"(r2), "=r"(r3) : "r"(addr));
}
__device__ __forceinline__ void ldm_x4t(uint32_t& r0, uint32_t& r1, uint32_t& r2,
                                        uint32_t& r3, uint32_t addr) {
    asm volatile("ldmatrix.sync.aligned.m8n8.x4.trans.shared.b16 {%0,%1,%2,%3}, [%4];"
        : "=r"(r0), "=r"(r1), "=r"(r2), "=r"(r3) : "r"(addr));
}
__device__ __forceinline__ void mma_bf16(float* c, const uint32_t* a, const uint32_t* b) {
    asm volatile("mma.sync.aligned.m16n8k16.row.col.f32.bf16.bf16.f32 "
        "{%0,%1,%2,%3}, {%4,%5,%6,%7}, {%8,%9}, {%0,%1,%2,%3};"
        : "+f"(c[0]), "+f"(c[1]), "+f"(c[2]), "+f"(c[3])
        : "r"(a[0]), "r"(a[1]), "r"(a[2]), "r"(a[3]), "r"(b[0]), "r"(b[1]));
}
__device__ __forceinline__ void bsplit2(float a, float b, uint32_t& hi, uint32_t& lo) {
    __nv_bfloat162 h = __floats2bfloat162_rn(a, b);
    hi = *reinterpret_cast<uint32_t*>(&h);
    float ra = a - __bfloat162float(h.x);
    float rb = b - __bfloat162float(h.y);
    __nv_bfloat162 l = __floats2bfloat162_rn(ra, rb);
    lo = *reinterpret_cast<uint32_t*>(&l);
}
__device__ __forceinline__ void cp16(uint32_t sdst, const void* gsrc) {
    asm volatile("cp.async.cg.shared.global [%0], [%1], 16;" :: "r"(sdst), "l"(gsrc));
}
#define CP_COMMIT() asm volatile("cp.async.commit_group;" ::: "memory")
#define CP_WAIT0()  asm volatile("cp.async.wait_group 0;" ::: "memory")

// ---------------- device scratch (pre-split bf16) ----------------------------
__device__ uint4 g_WcH4[RROWS * 32];          // 144 x 256 bf16
__device__ uint4 g_WcL4[RROWS * 32];
__device__ uint4 g_KpH4[B_ * G_ * 64 * 24];   // A' per (b,g): 64 x 192, 384 B/row
__device__ uint4 g_KpL4[B_ * G_ * 64 * 24];
__device__ float g_bc[RROWS];

// ---------------- kernel A: fuse weights, 8-way k-split ---------------------
__global__ __launch_bounds__(1024) void fuse_weights(
        const float* __restrict__ W_reduce, const float* __restrict__ b_reduce,
        const float* __restrict__ W_span,   const float* __restrict__ b_span) {
    __shared__ float ws[RED_CH];
    __shared__ float2 ps[1024];
    const int r   = blockIdx.x;
    const int tid = threadIdx.x;
    if (tid < RED_CH) ws[tid] = W_span[r * RED_CH + tid];
    __syncthreads();

    const int c2 = tid & 127;
    const int o0 = (tid >> 7) * 16;
    const float2* Wr2 = (const float2*)W_reduce;
    float s0 = 0.f, s1 = 0.f;
    #pragma unroll
    for (int o = o0; o < o0 + 16; o++) {
        const float2 w = Wr2[o * 128 + c2];
        const float a = ws[o];
        s0 += a * w.x;
        s1 += a * w.y;
    }
    ps[tid] = make_float2(s0, s1);
    __syncthreads();

    if (tid < 128) {
        s0 = 0.f; s1 = 0.f;
        #pragma unroll
        for (int p = 0; p < 8; p++) {
            float2 t = ps[tid + p * 128];
            s0 += t.x; s1 += t.y;
        }
        uint32_t hi, lo;
        bsplit2(s0, s1, hi, lo);
        ((uint32_t*)g_WcH4)[r * 128 + tid] = hi;
        ((uint32_t*)g_WcL4)[r * 128 + tid] = lo;
    }
    if (tid < 32) {
        float s = 0.f;
        #pragma unroll
        for (int o = tid; o < RED_CH; o += 32) s += ws[o] * b_reduce[o];
        #pragma unroll
        for (int d = 16; d > 0; d >>= 1) s += __shfl_xor_sync(0xffffffffu, s, d);
        if (tid == 0) g_bc[r] = s + b_span[r];
    }
}

// ---------------- kernel B: ker GEMM + fold, 12 warps 3Mx4N ------------------
#define KSTR   144
#define KF_AH  0
#define KF_AL  20736
#define KF_BH  41472
#define KF_BL  50688
#define KF_BC  59904
#define KF_SMEM (KF_BC + 576)

__global__ __launch_bounds__(384, 2) void ker_fold(const float* __restrict__ x) {
    extern __shared__ char smem[];
    const uint32_t sb = smem_u32(smem);
    float* sbc = (float*)(smem + KF_BC);
    const int i0 = blockIdx.x;
    const int b  = blockIdx.y;
    const int tid = threadIdx.x;
    const int wid = tid >> 5, lane = tid & 31;
    const int wm = wid % 3;           // M block of 48 rows
    const int wn = wid / 3;           // N block of 16 cols (0..3)
    const int r  = lane & 15, hh = lane >> 4;

    if (tid < RROWS) sbc[tid] = g_bc[tid];

    float acc[3][2][4];
    #pragma unroll
    for (int mt = 0; mt < 3; mt++)
        #pragma unroll
        for (int nt = 0; nt < 2; nt++)
            #pragma unroll
            for (int e = 0; e < 4; e++) acc[mt][nt][e] = 0.f;

    // prefetch kt=0 x slice into regs (1024 chunks over 384 threads)
    float4 breg[3];
    #pragma unroll
    for (int it = 0; it < 3; it++) {
        const int e = tid + 384 * it;
        if (e < 1024) {
            const int c = e >> 4, f = e & 15;
            breg[it] = *(const float4*)&x[((size_t)b * CH + c) * HW + i0 * HWD + f * 4];
        }
    }

    #pragma unroll 1
    for (int kt = 0; kt < 4; kt++) {
        __syncthreads();
        // async stage Wc slice (1152 uint4 each = 3 x 384)
        #pragma unroll
        for (int it = 0; it < 3; it++) {
            const int e = tid + 384 * it;
            const int row = e >> 3, q = e & 7;
            cp16(sb + KF_AH + row * KSTR + q * 16, &g_WcH4[row * 32 + kt * 8 + q]);
            cp16(sb + KF_AL + row * KSTR + q * 16, &g_WcL4[row * 32 + kt * 8 + q]);
        }
        CP_COMMIT();
        // convert prefetched x regs -> smem B
        #pragma unroll
        for (int it = 0; it < 3; it++) {
            const int e = tid + 384 * it;
            if (e < 1024) {
                const int c = e >> 4, f = e & 15;
                const float4 v = breg[it];
                uint32_t h0, l0, h1, l1;
                bsplit2(v.x, v.y, h0, l0);
                bsplit2(v.z, v.w, h1, l1);
                *(uint2*)(smem + KF_BH + c * KSTR + f * 8) = make_uint2(h0, h1);
                *(uint2*)(smem + KF_BL + c * KSTR + f * 8) = make_uint2(l0, l1);
            }
        }
        if (kt < 3) {
            #pragma unroll
            for (int it = 0; it < 3; it++) {
                const int e = tid + 384 * it;
                if (e < 1024) {
                    const int c = e >> 4, f = e & 15;
                    breg[it] = *(const float4*)&x[((size_t)b * CH + (kt + 1) * 64 + c) * HW + i0 * HWD + f * 4];
                }
            }
        }
        CP_WAIT0();
        __syncthreads();

        #pragma unroll
        for (int kk = 0; kk < 4; kk++) {
            uint32_t bh[4], bl[4];
            const uint32_t bb = sb + KF_BH + (kk * 16 + r) * KSTR + wn * 32 + hh * 16;
            ldm_x4t(bh[0], bh[1], bh[2], bh[3], bb);
            ldm_x4t(bl[0], bl[1], bl[2], bl[3], bb + (KF_BL - KF_BH));
            #pragma unroll
            for (int mt = 0; mt < 3; mt++) {
                uint32_t ah[4], al[4];
                const uint32_t ab = sb + KF_AH + (wm * 48 + mt * 16 + r) * KSTR + kk * 32 + hh * 16;
                ldm_x4(ah[0], ah[1], ah[2], ah[3], ab);
                ldm_x4(al[0], al[1], al[2], al[3], ab + (KF_AL - KF_AH));
                #pragma unroll
                for (int nt = 0; nt < 2; nt++) {
                    mma_bf16(acc[mt][nt], ah, &bh[2 * nt]);
                    mma_bf16(acc[mt][nt], ah, &bl[2 * nt]);
                    mma_bf16(acc[mt][nt], al, &bh[2 * nt]);
                }
            }
        }
    }

    // ---- spill ker (+bias) to smem fp32 [144][68] ---------------------------
    __syncthreads();
    float* Ys = (float*)smem;
    {
        const int gq = lane >> 2;
        const int cb = (lane & 3) * 2;
        #pragma unroll
        for (int mt = 0; mt < 3; mt++) {
            const int row = wm * 48 + mt * 16 + gq;
            const float b0 = sbc[row], b1 = sbc[row + 8];
            #pragma unroll
            for (int nt = 0; nt < 2; nt++) {
                const int col = wn * 16 + nt * 8 + cb;
                *(float2*)&Ys[row * 68 + col]       = make_float2(acc[mt][nt][0] + b0, acc[mt][nt][1] + b0);
                *(float2*)&Ys[(row + 8) * 68 + col] = make_float2(acc[mt][nt][2] + b1, acc[mt][nt][3] + b1);
            }
        }
    }
    __syncthreads();

    // ---- fold over ki, write A' transposed: row i0, cols (kj*64+m) ---------
    if (tid < 256) {
        const int g  = tid >> 4;
        const int ms = (tid & 15) * 4;
        const size_t arow = ((size_t)(b * G_ + g) * 64 + i0) * 384;   // bytes
        #pragma unroll
        for (int kj = 0; kj < 3; kj++) {
            const float* y1 = Ys + (g * 9 + 3 + kj) * 68;
            const float* y0 = Ys + (g * 9 + kj) * 68;
            const float* y2 = Ys + (g * 9 + 6 + kj) * 68;
            float v[4];
            #pragma unroll
            for (int mm = 0; mm < 4; mm++) {
                const int m = ms + mm;
                float t = y1[m];
                if (m < 63) t += y0[m + 1];
                if (m > 0)  t += y2[m - 1];
                v[mm] = t;
            }
            uint32_t h0, l0, h1, l1;
            bsplit2(v[0], v[1], h0, l0);
            bsplit2(v[2], v[3], h1, l1);
            const uint32_t cb2 = (kj * 64 + ms) * 2;
            *(uint2*)((char*)g_KpH4 + arow + cb2) = make_uint2(h0, h1);
            *(uint2*)((char*)g_KpL4 + arow + cb2) = make_uint2(l0, l1);
        }
    }
}

// ---------------- kernel C: shifted-B GEMM, 4 channels per CTA ---------------
#define IA_STR  400
#define I_AH    0
#define I_AL    25600
#define I_BH    51200
#define I_BL    78848
#define SMEM_INV 106496

__global__ __launch_bounds__(256, 2) void inv_mma(const float* __restrict__ x,
                                                  float* __restrict__ out) {
    extern __shared__ char smem[];
    const uint32_t sb = smem_u32(smem);
    const int cq = blockIdx.x, g = blockIdx.y, b = blockIdx.z;
    const int tid  = threadIdx.x;
    const int wid  = tid >> 5, lane = tid & 31;
    const int wm   = wid & 3;          // i quadrant (16 rows)
    const int wn   = wid >> 2;         // j half (32 cols)
    const int ch0  = g * 16 + cq * 4;
    const float* xbase = x + ((size_t)(b * CH) + ch0) * HW;

    // ---- async A' copy once (pre-split, resident for all 4 channels) --------
    {
        const uint4* KH = g_KpH4 + (size_t)(b * G_ + g) * 1536;
        const uint4* KL = g_KpL4 + (size_t)(b * G_ + g) * 1536;
        #pragma unroll
        for (int it = 0; it < 6; it++) {
            const int e = tid + 256 * it;
            const int row = e / 24, q = e - row * 24;
            cp16(sb + I_AH + row * IA_STR + q * 16, KH + e);
            cp16(sb + I_AL + row * IA_STR + q * 16, KL + e);
        }
        CP_COMMIT();
    }

    int mArr[4], j0Arr[4];
    #pragma unroll
    for (int it = 0; it < 4; it++) {
        const int e = tid + 256 * it;
        mArr[it] = e >> 4;
        j0Arr[it] = (e & 15) << 2;
    }

    float4 v[4]; float am1[4], a4[4];
    #pragma unroll
    for (int it = 0; it < 4; it++) {
        const float* row = xbase + mArr[it] * 64;
        v[it]  = *(const float4*)&row[j0Arr[it]];
        am1[it] = (j0Arr[it] > 0)  ? row[j0Arr[it] - 1] : 0.f;
        a4[it]  = (j0Arr[it] < 60) ? row[j0Arr[it] + 4] : 0.f;
    }

    const int r  = lane & 15;
    const int hh = lane >> 4;
    const int gq = lane >> 2, cb = (lane & 3) * 2;
    const int i0 = wm * 16 + gq;

    #pragma unroll 1
    for (int cc = 0; cc < 4; cc++) {
        if (cc > 0) __syncthreads();
        // ---- build B'(cc) from prefetched regs ------------------------------
        #pragma unroll
        for (int it = 0; it < 4; it++) {
            const int m = mArr[it], j0 = j0Arr[it];
            uint32_t h[5], l[5];
            bsplit2(am1[it], v[it].x, h[0], l[0]);
            bsplit2(v[it].x, v[it].y, h[1], l[1]);
            bsplit2(v[it].y, v[it].z, h[2], l[2]);
            bsplit2(v[it].z, v[it].w, h[3], l[3]);
            bsplit2(v[it].w, a4[it],  h[4], l[4]);
            const uint32_t cbyte = j0 * 2;
            *(uint2*)(smem + I_BH + m * 144 + cbyte) = make_uint2(h[0], h[2]);
            *(uint2*)(smem + I_BL + m * 144 + cbyte) = make_uint2(l[0], l[2]);
            *(uint2*)(smem + I_BH + (64 + m) * 144 + cbyte) = make_uint2(h[1], h[3]);
            *(uint2*)(smem + I_BL + (64 + m) * 144 + cbyte) = make_uint2(l[1], l[3]);
            *(uint2*)(smem + I_BH + (128 + m) * 144 + cbyte) = make_uint2(h[2], h[4]);
            *(uint2*)(smem + I_BL + (128 + m) * 144 + cbyte) = make_uint2(l[2], l[4]);
        }
        if (cc == 0) CP_WAIT0();
        __syncthreads();

        // ---- prefetch x(cc+1) (hidden under MMA) -----------------------------
        if (cc < 3) {
            const float* xn = xbase + (cc + 1) * HW;
            #pragma unroll
            for (int it = 0; it < 4; it++) {
                const float* row = xn + mArr[it] * 64;
                v[it]  = *(const float4*)&row[j0Arr[it]];
                am1[it] = (j0Arr[it] > 0)  ? row[j0Arr[it] - 1] : 0.f;
                a4[it]  = (j0Arr[it] < 60) ? row[j0Arr[it] + 4] : 0.f;
            }
        }

        // ---- K=192 mma -------------------------------------------------------
        float acc[4][4];
        #pragma unroll
        for (int nt = 0; nt < 4; nt++)
            #pragma unroll
            for (int e = 0; e < 4; e++) acc[nt][e] = 0.f;

        #pragma unroll
        for (int k = 0; k < 12; k++) {
            uint32_t ah[4], al[4];
            const uint32_t abase = sb + I_AH + (wm * 16 + r) * IA_STR + k * 32 + hh * 16;
            ldm_x4(ah[0], ah[1], ah[2], ah[3], abase);
            ldm_x4(al[0], al[1], al[2], al[3], abase + (I_AL - I_AH));
            uint32_t bh[4][2], bl[4][2];
            #pragma unroll
            for (int ntp = 0; ntp < 2; ntp++) {
                const uint32_t bb = sb + I_BH + (k * 16 + r) * 144 + wn * 64 + ntp * 32 + hh * 16;
                ldm_x4t(bh[2*ntp][0], bh[2*ntp][1], bh[2*ntp+1][0], bh[2*ntp+1][1], bb);
                ldm_x4t(bl[2*ntp][0], bl[2*ntp][1], bl[2*ntp+1][0], bl[2*ntp+1][1],
                        bb + (I_BL - I_BH));
            }
            #pragma unroll
            for (int nt = 0; nt < 4; nt++) {
                mma_bf16(acc[nt], ah, bh[nt]);
                mma_bf16(acc[nt], ah, bl[nt]);
                mma_bf16(acc[nt], al, bh[nt]);
            }
        }

        // ---- direct store -----------------------------------------------------
        float* op = out + ((size_t)(b * CH) + ch0 + cc) * HW;
        #pragma unroll
        for (int nt = 0; nt < 4; nt++) {
            const int j = wn * 32 + nt * 8 + cb;
            *(float2*)&op[i0 * 64 + j]       = make_float2(acc[nt][0], acc[nt][1]);
            *(float2*)&op[(i0 + 8) * 64 + j] = make_float2(acc[nt][2], acc[nt][3]);
        }
    }
}

// ---------------- launch ------------------------------------------------------
extern "C" void kernel_launch(void* const* d_in, const int* in_sizes, int n_in,
                              void* d_out, int out_size) {
    const float* x        = (const float*)d_in[0];
    const float* W_reduce = (const float*)d_in[1];
    const float* b_reduce = (const float*)d_in[2];
    const float* W_span   = (const float*)d_in[3];
    const float* b_span   = (const float*)d_in[4];
    float* out = (float*)d_out;

    cudaFuncSetAttribute(ker_fold, cudaFuncAttributeMaxDynamicSharedMemorySize, KF_SMEM);
    cudaFuncSetAttribute(inv_mma,  cudaFuncAttributeMaxDynamicSharedMemorySize, SMEM_INV);

    fuse_weights<<<RROWS, 1024>>>(W_reduce, b_reduce, W_span, b_span);
    ker_fold<<<dim3(HWD, B_), 384, KF_SMEM>>>(x);
    inv_mma<<<dim3(4, G_, B_), 256, SMEM_INV>>>(x, out);
}

// round 12
// speedup vs baseline: 5.0827x; 1.2144x over previous
#include <cuda_runtime.h>
#include <cuda_fp16.h>
#include <cstdint>

// Problem constants
#define CH      256
#define G_      16
#define RROWS   144
#define RED_CH  128
#define B_      8
#define HWD     64
#define HW      4096

// ---------------- mma.sync / async helpers -----------------------------------
__device__ __forceinline__ uint32_t smem_u32(const void* p) {
    uint32_t a;
    asm("{ .reg .u64 t; cvta.to.shared.u64 t, %1; cvt.u32.u64 %0, t; }" : "=r"(a) : "l"(p));
    return a;
}
__device__ __forceinline__ void ldm_x4(uint32_t& r0, uint32_t& r1, uint32_t& r2,
                                       uint32_t& r3, uint32_t addr) {
    asm volatile("ldmatrix.sync.aligned.m8n8.x4.shared.b16 {%0,%1,%2,%3}, [%4];"
        : "=r"(r0), "=r"(r1), "=r"(r2), "=r"(r3) : "r"(addr));
}
__device__ __forceinline__ void ldm_x4t(uint32_t& r0, uint32_t& r1, uint32_t& r2,
                                        uint32_t& r3, uint32_t addr) {
    asm volatile("ldmatrix.sync.aligned.m8n8.x4.trans.shared.b16 {%0,%1,%2,%3}, [%4];"
        : "=r"(r0), "=r"(r1), "=r"(r2), "=r"(r3) : "r"(addr));
}
__device__ __forceinline__ void mma_f16(float* c, const uint32_t* a, const uint32_t* b) {
    asm volatile("mma.sync.aligned.m16n8k16.row.col.f32.f16.f16.f32 "
        "{%0,%1,%2,%3}, {%4,%5,%6,%7}, {%8,%9}, {%0,%1,%2,%3};"
        : "+f"(c[0]), "+f"(c[1]), "+f"(c[2]), "+f"(c[3])
        : "r"(a[0]), "r"(a[1]), "r"(a[2]), "r"(a[3]), "r"(b[0]), "r"(b[1]));
}
// fp16 split of two floats: hi = rn(a), lo = rn(a - hi)
__device__ __forceinline__ void fsplit2(float a, float b, uint32_t& hi, uint32_t& lo) {
    __half2 h = __floats2half2_rn(a, b);
    hi = *reinterpret_cast<uint32_t*>(&h);
    float ra = a - __half2float(__low2half(h));
    float rb = b - __half2float(__high2half(h));
    __half2 l = __floats2half2_rn(ra, rb);
    lo = *reinterpret_cast<uint32_t*>(&l);
}
__device__ __forceinline__ uint32_t fpack2(float a, float b) {
    __half2 h = __floats2half2_rn(a, b);
    return *reinterpret_cast<uint32_t*>(&h);
}
__device__ __forceinline__ void cp16(uint32_t sdst, const void* gsrc) {
    asm volatile("cp.async.cg.shared.global [%0], [%1], 16;" :: "r"(sdst), "l"(gsrc));
}
#define CP_COMMIT() asm volatile("cp.async.commit_group;" ::: "memory")
#define CP_WAIT0()  asm volatile("cp.async.wait_group 0;" ::: "memory")

// ---------------- device scratch (pre-split fp16) ----------------------------
__device__ uint4 g_WcH4[RROWS * 32];          // Wc ah: 144 x 256 fp16
__device__ uint4 g_WcL4[RROWS * 32];          // Wc al
__device__ uint4 g_KpH4[B_ * G_ * 64 * 24];   // A' ah per (b,g): 64 x 192, 384 B/row
__device__ uint4 g_KpL4[B_ * G_ * 64 * 24];   // A' al
__device__ float g_bc[RROWS];

// ---------------- kernel A: fuse weights, 8-way k-split ---------------------
__global__ __launch_bounds__(1024) void fuse_weights(
        const float* __restrict__ W_reduce, const float* __restrict__ b_reduce,
        const float* __restrict__ W_span,   const float* __restrict__ b_span) {
    __shared__ float ws[RED_CH];
    __shared__ float2 ps[1024];
    const int r   = blockIdx.x;
    const int tid = threadIdx.x;
    if (tid < RED_CH) ws[tid] = W_span[r * RED_CH + tid];
    __syncthreads();

    const int c2 = tid & 127;
    const int o0 = (tid >> 7) * 16;
    const float2* Wr2 = (const float2*)W_reduce;
    float s0 = 0.f, s1 = 0.f;
    #pragma unroll
    for (int o = o0; o < o0 + 16; o++) {
        const float2 w = Wr2[o * 128 + c2];
        const float a = ws[o];
        s0 += a * w.x;
        s1 += a * w.y;
    }
    ps[tid] = make_float2(s0, s1);
    __syncthreads();

    if (tid < 128) {
        s0 = 0.f; s1 = 0.f;
        #pragma unroll
        for (int p = 0; p < 8; p++) {
            float2 t = ps[tid + p * 128];
            s0 += t.x; s1 += t.y;
        }
        uint32_t hi, lo;
        fsplit2(s0, s1, hi, lo);
        ((uint32_t*)g_WcH4)[r * 128 + tid] = hi;
        ((uint32_t*)g_WcL4)[r * 128 + tid] = lo;
    }
    if (tid < 32) {
        float s = 0.f;
        #pragma unroll
        for (int o = tid; o < RED_CH; o += 32) s += ws[o] * b_reduce[o];
        #pragma unroll
        for (int d = 16; d > 0; d >>= 1) s += __shfl_xor_sync(0xffffffffu, s, d);
        if (tid == 0) g_bc[r] = s + b_span[r];
    }
}

// ---------------- kernel B: ker GEMM + fold, fp16 2-pass ---------------------
#define KSTR   144
#define KF_AH  0
#define KF_AL  20736
#define KF_B   41472          // x single fp16: 64 x 144B
#define KF_BC  50688
#define KF_SMEM (KF_BC + 576)

__global__ __launch_bounds__(384, 2) void ker_fold(const float* __restrict__ x) {
    extern __shared__ char smem[];
    const uint32_t sb = smem_u32(smem);
    float* sbc = (float*)(smem + KF_BC);
    const int i0 = blockIdx.x;
    const int b  = blockIdx.y;
    const int tid = threadIdx.x;
    const int wid = tid >> 5, lane = tid & 31;
    const int wm = wid % 3;           // M block of 48 rows
    const int wn = wid / 3;           // N block of 16 cols (0..3)
    const int r  = lane & 15, hh = lane >> 4;

    if (tid < RROWS) sbc[tid] = g_bc[tid];

    float acc[3][2][4];
    #pragma unroll
    for (int mt = 0; mt < 3; mt++)
        #pragma unroll
        for (int nt = 0; nt < 2; nt++)
            #pragma unroll
            for (int e = 0; e < 4; e++) acc[mt][nt][e] = 0.f;

    // prefetch kt=0 x slice into regs (1024 chunks over 384 threads)
    float4 breg[3];
    #pragma unroll
    for (int it = 0; it < 3; it++) {
        const int e = tid + 384 * it;
        if (e < 1024) {
            const int c = e >> 4, f = e & 15;
            breg[it] = *(const float4*)&x[((size_t)b * CH + c) * HW + i0 * HWD + f * 4];
        }
    }

    #pragma unroll 1
    for (int kt = 0; kt < 4; kt++) {
        __syncthreads();
        // async stage Wc slice (1152 uint4 each = 3 x 384)
        #pragma unroll
        for (int it = 0; it < 3; it++) {
            const int e = tid + 384 * it;
            const int row = e >> 3, q = e & 7;
            cp16(sb + KF_AH + row * KSTR + q * 16, &g_WcH4[row * 32 + kt * 8 + q]);
            cp16(sb + KF_AL + row * KSTR + q * 16, &g_WcL4[row * 32 + kt * 8 + q]);
        }
        CP_COMMIT();
        // convert prefetched x regs -> smem B (single fp16)
        #pragma unroll
        for (int it = 0; it < 3; it++) {
            const int e = tid + 384 * it;
            if (e < 1024) {
                const int c = e >> 4, f = e & 15;
                const float4 v = breg[it];
                *(uint2*)(smem + KF_B + c * KSTR + f * 8) =
                    make_uint2(fpack2(v.x, v.y), fpack2(v.z, v.w));
            }
        }
        if (kt < 3) {
            #pragma unroll
            for (int it = 0; it < 3; it++) {
                const int e = tid + 384 * it;
                if (e < 1024) {
                    const int c = e >> 4, f = e & 15;
                    breg[it] = *(const float4*)&x[((size_t)b * CH + (kt + 1) * 64 + c) * HW + i0 * HWD + f * 4];
                }
            }
        }
        CP_WAIT0();
        __syncthreads();

        #pragma unroll
        for (int kk = 0; kk < 4; kk++) {
            uint32_t bh[4];
            const uint32_t bb = sb + KF_B + (kk * 16 + r) * KSTR + wn * 32 + hh * 16;
            ldm_x4t(bh[0], bh[1], bh[2], bh[3], bb);
            #pragma unroll
            for (int mt = 0; mt < 3; mt++) {
                uint32_t ah[4], al[4];
                const uint32_t ab = sb + KF_AH + (wm * 48 + mt * 16 + r) * KSTR + kk * 32 + hh * 16;
                ldm_x4(ah[0], ah[1], ah[2], ah[3], ab);
                ldm_x4(al[0], al[1], al[2], al[3], ab + (KF_AL - KF_AH));
                #pragma unroll
                for (int nt = 0; nt < 2; nt++) {
                    mma_f16(acc[mt][nt], ah, &bh[2 * nt]);
                    mma_f16(acc[mt][nt], al, &bh[2 * nt]);
                }
            }
        }
    }

    // ---- spill ker (+bias) to smem fp32 [144][68] ---------------------------
    __syncthreads();
    float* Ys = (float*)smem;
    {
        const int gq = lane >> 2;
        const int cb = (lane & 3) * 2;
        #pragma unroll
        for (int mt = 0; mt < 3; mt++) {
            const int row = wm * 48 + mt * 16 + gq;
            const float b0 = sbc[row], b1 = sbc[row + 8];
            #pragma unroll
            for (int nt = 0; nt < 2; nt++) {
                const int col = wn * 16 + nt * 8 + cb;
                *(float2*)&Ys[row * 68 + col]       = make_float2(acc[mt][nt][0] + b0, acc[mt][nt][1] + b0);
                *(float2*)&Ys[(row + 8) * 68 + col] = make_float2(acc[mt][nt][2] + b1, acc[mt][nt][3] + b1);
            }
        }
    }
    __syncthreads();

    // ---- fold over ki, write A' transposed fp16-split -----------------------
    if (tid < 256) {
        const int g  = tid >> 4;
        const int ms = (tid & 15) * 4;
        const size_t arow = ((size_t)(b * G_ + g) * 64 + i0) * 384;   // bytes
        #pragma unroll
        for (int kj = 0; kj < 3; kj++) {
            const float* y1 = Ys + (g * 9 + 3 + kj) * 68;
            const float* y0 = Ys + (g * 9 + kj) * 68;
            const float* y2 = Ys + (g * 9 + 6 + kj) * 68;
            float v[4];
            #pragma unroll
            for (int mm = 0; mm < 4; mm++) {
                const int m = ms + mm;
                float t = y1[m];
                if (m < 63) t += y0[m + 1];
                if (m > 0)  t += y2[m - 1];
                v[mm] = t;
            }
            uint32_t h0, l0, h1, l1;
            fsplit2(v[0], v[1], h0, l0);
            fsplit2(v[2], v[3], h1, l1);
            const uint32_t cb2 = (kj * 64 + ms) * 2;
            *(uint2*)((char*)g_KpH4 + arow + cb2) = make_uint2(h0, h1);
            *(uint2*)((char*)g_KpL4 + arow + cb2) = make_uint2(l0, l1);
        }
    }
}

// ---------------- kernel C: shifted-B GEMM, fp16 2-pass, 4 ch/CTA ------------
#define IA_STR  400
#define I_AH    0
#define I_AL    25600
#define I_B     51200          // B' single fp16: 192 x 144B
#define SMEM_INV 78848

__global__ __launch_bounds__(256, 2) void inv_mma(const float* __restrict__ x,
                                                  float* __restrict__ out) {
    extern __shared__ char smem[];
    const uint32_t sb = smem_u32(smem);
    const int cq = blockIdx.x, g = blockIdx.y, b = blockIdx.z;
    const int tid  = threadIdx.x;
    const int wid  = tid >> 5, lane = tid & 31;
    const int wm   = wid & 3;          // i quadrant (16 rows)
    const int wn   = wid >> 2;         // j half (32 cols)
    const int ch0  = g * 16 + cq * 4;
    const float* xbase = x + ((size_t)(b * CH) + ch0) * HW;

    // ---- async A' copy once (pre-split, resident for all 4 channels) --------
    {
        const uint4* KH = g_KpH4 + (size_t)(b * G_ + g) * 1536;
        const uint4* KL = g_KpL4 + (size_t)(b * G_ + g) * 1536;
        #pragma unroll
        for (int it = 0; it < 6; it++) {
            const int e = tid + 256 * it;
            const int row = e / 24, q = e - row * 24;
            cp16(sb + I_AH + row * IA_STR + q * 16, KH + e);
            cp16(sb + I_AL + row * IA_STR + q * 16, KL + e);
        }
        CP_COMMIT();
    }

    int mArr[4], j0Arr[4];
    #pragma unroll
    for (int it = 0; it < 4; it++) {
        const int e = tid + 256 * it;
        mArr[it] = e >> 4;
        j0Arr[it] = (e & 15) << 2;
    }

    float4 v[4]; float am1[4], a4[4];
    #pragma unroll
    for (int it = 0; it < 4; it++) {
        const float* row = xbase + mArr[it] * 64;
        v[it]  = *(const float4*)&row[j0Arr[it]];
        am1[it] = (j0Arr[it] > 0)  ? row[j0Arr[it] - 1] : 0.f;
        a4[it]  = (j0Arr[it] < 60) ? row[j0Arr[it] + 4] : 0.f;
    }

    const int r  = lane & 15;
    const int hh = lane >> 4;
    const int gq = lane >> 2, cb = (lane & 3) * 2;
    const int i0 = wm * 16 + gq;

    #pragma unroll 1
    for (int cc = 0; cc < 4; cc++) {
        if (cc > 0) __syncthreads();
        // ---- build B'(cc): single fp16, 3 shifted copies ---------------------
        #pragma unroll
        for (int it = 0; it < 4; it++) {
            const int m = mArr[it], j0 = j0Arr[it];
            uint32_t p0 = fpack2(am1[it], v[it].x);
            uint32_t p1 = fpack2(v[it].x, v[it].y);
            uint32_t p2 = fpack2(v[it].y, v[it].z);
            uint32_t p3 = fpack2(v[it].z, v[it].w);
            uint32_t p4 = fpack2(v[it].w, a4[it]);
            const uint32_t cbyte = j0 * 2;
            *(uint2*)(smem + I_B + m * 144 + cbyte)         = make_uint2(p0, p2);
            *(uint2*)(smem + I_B + (64 + m) * 144 + cbyte)  = make_uint2(p1, p3);
            *(uint2*)(smem + I_B + (128 + m) * 144 + cbyte) = make_uint2(p2, p4);
        }
        if (cc == 0) CP_WAIT0();
        __syncthreads();

        // ---- prefetch x(cc+1) (hidden under MMA) -----------------------------
        if (cc < 3) {
            const float* xn = xbase + (cc + 1) * HW;
            #pragma unroll
            for (int it = 0; it < 4; it++) {
                const float* row = xn + mArr[it] * 64;
                v[it]  = *(const float4*)&row[j0Arr[it]];
                am1[it] = (j0Arr[it] > 0)  ? row[j0Arr[it] - 1] : 0.f;
                a4[it]  = (j0Arr[it] < 60) ? row[j0Arr[it] + 4] : 0.f;
            }
        }

        // ---- K=192 mma, fp16 2-pass -----------------------------------------
        float acc[4][4];
        #pragma unroll
        for (int nt = 0; nt < 4; nt++)
            #pragma unroll
            for (int e = 0; e < 4; e++) acc[nt][e] = 0.f;

        #pragma unroll
        for (int k = 0; k < 12; k++) {
            uint32_t ah[4], al[4];
            const uint32_t abase = sb + I_AH + (wm * 16 + r) * IA_STR + k * 32 + hh * 16;
            ldm_x4(ah[0], ah[1], ah[2], ah[3], abase);
            ldm_x4(al[0], al[1], al[2], al[3], abase + (I_AL - I_AH));
            uint32_t bh[4][2];
            #pragma unroll
            for (int ntp = 0; ntp < 2; ntp++) {
                const uint32_t bb = sb + I_B + (k * 16 + r) * 144 + wn * 64 + ntp * 32 + hh * 16;
                ldm_x4t(bh[2*ntp][0], bh[2*ntp][1], bh[2*ntp+1][0], bh[2*ntp+1][1], bb);
            }
            #pragma unroll
            for (int nt = 0; nt < 4; nt++) {
                mma_f16(acc[nt], ah, bh[nt]);
                mma_f16(acc[nt], al, bh[nt]);
            }
        }

        // ---- direct store -----------------------------------------------------
        float* op = out + ((size_t)(b * CH) + ch0 + cc) * HW;
        #pragma unroll
        for (int nt = 0; nt < 4; nt++) {
            const int j = wn * 32 + nt * 8 + cb;
            *(float2*)&op[i0 * 64 + j]       = make_float2(acc[nt][0], acc[nt][1]);
            *(float2*)&op[(i0 + 8) * 64 + j] = make_float2(acc[nt][2], acc[nt][3]);
        }
    }
}

// ---------------- launch ------------------------------------------------------
extern "C" void kernel_launch(void* const* d_in, const int* in_sizes, int n_in,
                              void* d_out, int out_size) {
    const float* x        = (const float*)d_in[0];
    const float* W_reduce = (const float*)d_in[1];
    const float* b_reduce = (const float*)d_in[2];
    const float* W_span   = (const float*)d_in[3];
    const float* b_span   = (const float*)d_in[4];
    float* out = (float*)d_out;

    cudaFuncSetAttribute(ker_fold, cudaFuncAttributeMaxDynamicSharedMemorySize, KF_SMEM);
    cudaFuncSetAttribute(inv_mma,  cudaFuncAttributeMaxDynamicSharedMemorySize, SMEM_INV);

    fuse_weights<<<RROWS, 1024>>>(W_reduce, b_reduce, W_span, b_span);
    ker_fold<<<dim3(HWD, B_), 384, KF_SMEM>>>(x);
    inv_mma<<<dim3(4, G_, B_), 256, SMEM_INV>>>(x, out);
}